// round 13
// baseline (speedup 1.0000x reference)
#include <cuda_runtime.h>
#include <cuda_fp16.h>
#include <stdint.h>
#include <math.h>

#define NTOK 2048
#define EDIM 1024
#define NLAYER 4

// ---------------------------------------------------------------------------
// Scratch (device globals — allocation is forbidden). Pure fp16 operands.
// ---------------------------------------------------------------------------
__device__ __half g_x[NTOK * EDIM];
__device__ __half g_qkv[NTOK * 3 * EDIM];
__device__ float  g_p0[NTOK * 3 * EDIM];   // qkv(x2) / scores(x4) partials
__device__ float  g_p1[NTOK * 3 * EDIM];
__device__ float  g_p2[NTOK * NTOK];       // scores partials 2,3
__device__ float  g_p3[NTOK * NTOK];
__device__ float  g_sp0[NTOK * EDIM];      // wv(x4) / out-proj(x2) partials
__device__ float  g_sp1[NTOK * EDIM];
__device__ float  g_sp2[NTOK * EDIM];
__device__ float  g_sp3[NTOK * EDIM];
__device__ __half g_wh[NTOK * NTOK];
__device__ __half g_vT[EDIM * NTOK];
__device__ __half g_wv[NTOK * EDIM];
__device__ __half g_Wqkv[NLAYER * 3 * EDIM * EDIM];
__device__ __half g_Wo[NLAYER * EDIM * EDIM];

// ---------------------------------------------------------------------------
// Helpers
// ---------------------------------------------------------------------------
__device__ __forceinline__ uint32_t s2u(const void* p) {
    uint32_t a;
    asm("{ .reg .u64 t; cvta.to.shared.u64 t, %1; cvt.u32.u64 %0, t; }" : "=r"(a) : "l"(p));
    return a;
}
#define CPA(sm, gp) \
    asm volatile("cp.async.cg.shared.global [%0], [%1], 16;" :: "r"(sm), "l"(gp))
#define CPA_COMMIT() asm volatile("cp.async.commit_group;")
#define CPA_WAIT2()  asm volatile("cp.async.wait_group 2;")

#define LDSM4(r0, r1, r2, r3, addr)                                          \
    asm volatile("ldmatrix.sync.aligned.m8n8.x4.shared.b16 {%0,%1,%2,%3}, [%4];" \
                 : "=r"(r0), "=r"(r1), "=r"(r2), "=r"(r3) : "r"(addr))

__device__ __forceinline__ void mma16816(float* c, const uint32_t* a, const uint32_t* b) {
    asm volatile(
        "mma.sync.aligned.m16n8k16.row.col.f32.f16.f16.f32 "
        "{%0,%1,%2,%3}, {%4,%5,%6,%7}, {%8,%9}, {%0,%1,%2,%3};"
        : "+f"(c[0]), "+f"(c[1]), "+f"(c[2]), "+f"(c[3])
        : "r"(a[0]), "r"(a[1]), "r"(a[2]), "r"(a[3]), "r"(b[0]), "r"(b[1]));
}

__device__ __forceinline__ uint32_t pack2h(float a, float b) {
    __half2 t = __floats2half2_rn(a, b);
    return *reinterpret_cast<uint32_t*>(&t);
}

// SMEM: 4 stages; stage = 2 tiles (A, B) of 128 rows x 16 fp16, 48B pitch.
// (R8 mainloop configuration: best measured. DO NOT TOUCH.)
#define TILE_B   6144          // 128 * 48
#define STAGE_B  12288         // 2 tiles
#define SMEM_BYTES (4 * STAGE_B)   // 49152

// ---------------------------------------------------------------------------
// Split-K (xNSPLIT) tensor-core NT GEMM, single-pass fp16 (R8 mainloop):
//   partial[kz] = sum_{k in slice kz} A*B^T   (fp32 out)
//   CSKIP: skip blocks strictly above diagonal;  KLIM: Keff = (by+1)*128
// 4-stage cp.async pipeline, ONE __syncthreads per K=16 chunk.
// Prologue is guarded (supports nch >= 2).
// ---------------------------------------------------------------------------
template<int NSPLIT, bool CSKIP, bool KLIM>
__global__ void __launch_bounds__(256, 2) gemm_mma(
    const __half* __restrict__ A, int lda,
    const __half* __restrict__ B, int ldb,
    float* __restrict__ Cf0, float* __restrict__ Cf1,
    float* __restrict__ Cf2, float* __restrict__ Cf3, int ldc,
    int K, float alpha)
{
    const int bx = blockIdx.x, by = blockIdx.y, kz = blockIdx.z;
    if (CSKIP && bx > by) return;
    const int Keff  = KLIM ? min(K, (by + 1) * 128) : K;
    const int slice = Keff / NSPLIT;       // multiple of 32
    const int k0    = kz * slice;
    const int nch   = slice / 16;          // >= 2 in all uses

    float* __restrict__ Cp = (kz == 0) ? Cf0 : (kz == 1) ? Cf1
                           : (kz == 2) ? Cf2 : Cf3;

    extern __shared__ __align__(128) char smem[];
    const uint32_t sb = s2u(smem);

    const int tid  = threadIdx.x;
    const int wid  = tid >> 5, lane = tid & 31;
    const int wm   = (wid & 1) * 64;
    const int wn   = (wid >> 1) * 32;

    const __half* Ab = A + (size_t)(by * 128) * lda;
    const __half* Bb = B + (size_t)(bx * 128) * ldb;

    const uint32_t a_row = lane & 15;
    const uint32_t a_k   = (lane >> 4) * 16;
    const uint32_t b_row = (lane & 7) + (lane >> 4) * 8;
    const uint32_t b_k   = ((lane >> 3) & 1) * 16;

    float acc[4][4][4];
#pragma unroll
    for (int i = 0; i < 4; i++)
#pragma unroll
        for (int j = 0; j < 4; j++)
#pragma unroll
            for (int r = 0; r < 4; r++) acc[i][j][r] = 0.f;

    const int lrow = tid >> 1;
    const int lc   = tid & 1;
    const uint32_t lso = (uint32_t)lrow * 48 + lc * 16;
    const size_t   lga = (size_t)lrow * lda + lc * 8;
    const size_t   lgb = (size_t)lrow * ldb + lc * 8;

    auto load_stage = [&](int stage, int kt) {
        uint32_t base = sb + (uint32_t)stage * STAGE_B + lso;
        CPA(base,          Ab + lga + kt);
        CPA(base + TILE_B, Bb + lgb + kt);
    };

    // guarded prologue: supports nch >= 2 (empty groups keep count uniform)
#pragma unroll
    for (int s = 0; s < 3; s++) {
        if (s < nch) load_stage(s, k0 + s * 16);
        CPA_COMMIT();
    }

    for (int c = 0; c < nch; c++) {
        CPA_WAIT2();
        __syncthreads();
        if (c + 3 < nch) load_stage((c + 3) & 3, k0 + (c + 3) * 16);
        CPA_COMMIT();

        const uint32_t base = sb + (uint32_t)(c & 3) * STAGE_B;

        uint32_t bf[8];
        {
            uint32_t bb = base + TILE_B + (wn + b_row) * 48 + b_k;
            LDSM4(bf[0], bf[1], bf[2], bf[3], bb);
            LDSM4(bf[4], bf[5], bf[6], bf[7], bb + 16 * 48);
        }
#pragma unroll
        for (int mf = 0; mf < 4; mf++) {
            uint32_t ah[4];
            uint32_t ab = base + (wm + mf * 16 + a_row) * 48 + a_k;
            LDSM4(ah[0], ah[1], ah[2], ah[3], ab);
#pragma unroll
            for (int nf = 0; nf < 4; nf++)
                mma16816(acc[mf][nf], ah, bf + nf * 2);
        }
    }

#pragma unroll
    for (int mf = 0; mf < 4; mf++) {
#pragma unroll
        for (int nf = 0; nf < 4; nf++) {
            const float* cc = acc[mf][nf];
            int row0 = by * 128 + wm + mf * 16 + (lane >> 2);
            int col  = bx * 128 + wn + nf * 8 + (lane & 3) * 2;
            float2 v0 = make_float2(alpha * cc[0], alpha * cc[1]);
            float2 v1 = make_float2(alpha * cc[2], alpha * cc[3]);
            *(float2*)(Cp + (size_t)row0 * ldc + col) = v0;
            *(float2*)(Cp + (size_t)(row0 + 8) * ldc + col) = v1;
        }
    }
}

// ---------------------------------------------------------------------------
// Fused qkv combine + v transpose (R11 kernel, unchanged; 2 partials).
// ---------------------------------------------------------------------------
__global__ __launch_bounds__(256) void combine_qkv_transpose(
    const float* __restrict__ p0, const float* __restrict__ p1,
    const float* __restrict__ bias,
    __half* __restrict__ qkv, __half* __restrict__ vT)
{
    __shared__ __half sh[64][65];
    const int c0 = blockIdx.x * 64, r0 = blockIdx.y * 64;
    const int tid = threadIdx.x;
    const int col4 = tid & 15;
    const int rbase = tid >> 4;
    const bool vtile = (c0 >= 2 * EDIM);

    float b0 = bias[c0 + col4 * 4 + 0];
    float b1 = bias[c0 + col4 * 4 + 1];
    float b2 = bias[c0 + col4 * 4 + 2];
    float b3 = bias[c0 + col4 * 4 + 3];

#pragma unroll
    for (int rr = 0; rr < 4; rr++) {
        int r = rbase + rr * 16;
        size_t idx4 = ((size_t)(r0 + r) * (3 * EDIM) + c0 + col4 * 4) >> 2;
        float4 a = ((const float4*)p0)[idx4];
        float4 b = ((const float4*)p1)[idx4];
        float v0 = a.x + b.x + b0, v1 = a.y + b.y + b1;
        float v2 = a.z + b.z + b2, v3 = a.w + b.w + b3;
        uint2 ph;
        ph.x = pack2h(v0, v1); ph.y = pack2h(v2, v3);
        ((uint2*)qkv)[idx4] = ph;
        if (vtile) {
            __half2 h01 = __floats2half2_rn(v0, v1);
            __half2 h23 = __floats2half2_rn(v2, v3);
            sh[r][col4 * 4 + 0] = __low2half(h01);
            sh[r][col4 * 4 + 1] = __high2half(h01);
            sh[r][col4 * 4 + 2] = __low2half(h23);
            sh[r][col4 * 4 + 3] = __high2half(h23);
        }
    }

    if (vtile) {
        __syncthreads();
        const int cc = tid & 63;
        const int rg = tid >> 6;
        __half tmp[16];
#pragma unroll
        for (int j = 0; j < 16; j++) tmp[j] = sh[rg * 16 + j][cc];
        size_t dst = (size_t)(c0 - 2 * EDIM + cc) * NTOK + r0 + rg * 16;
        *(uint4*)(vT + dst)     = *(uint4*)&tmp[0];
        *(uint4*)(vT + dst + 8) = *(uint4*)&tmp[8];
    }
}

// ---------------------------------------------------------------------------
// combine 4 split-K partials: v = (p0+p1)+(p2+p3) (+ bias); write fp16
// ---------------------------------------------------------------------------
__global__ void combine_split4(const float* __restrict__ p0, const float* __restrict__ p1,
                               const float* __restrict__ p2, const float* __restrict__ p3,
                               const float* __restrict__ bias,
                               __half* __restrict__ dst, int ncols, int n4)
{
    int idx = blockIdx.x * blockDim.x + threadIdx.x;
    if (idx >= n4) return;
    float4 a = ((const float4*)p0)[idx];
    float4 b = ((const float4*)p1)[idx];
    float4 c = ((const float4*)p2)[idx];
    float4 d = ((const float4*)p3)[idx];
    float v0 = (a.x + b.x) + (c.x + d.x);
    float v1 = (a.y + b.y) + (c.y + d.y);
    float v2 = (a.z + b.z) + (c.z + d.z);
    float v3 = (a.w + b.w) + (c.w + d.w);
    if (bias) {
        int col = (idx * 4) % ncols;
        v0 += bias[col]; v1 += bias[col + 1]; v2 += bias[col + 2]; v3 += bias[col + 3];
    }
    uint2 ph;
    ph.x = pack2h(v0, v1); ph.y = pack2h(v2, v3);
    ((uint2*)dst)[idx] = ph;
}

// combine 2 split-K partials (out-proj / wv path when ×2)
__global__ void combine_split(const float* __restrict__ p0, const float* __restrict__ p1,
                              const float* __restrict__ bias,
                              __half* __restrict__ dst, int ncols, int n4)
{
    int idx = blockIdx.x * blockDim.x + threadIdx.x;
    if (idx >= n4) return;
    float4 a = ((const float4*)p0)[idx];
    float4 b = ((const float4*)p1)[idx];
    float v0 = a.x + b.x, v1 = a.y + b.y, v2 = a.z + b.z, v3 = a.w + b.w;
    if (bias) {
        int col = (idx * 4) % ncols;
        v0 += bias[col]; v1 += bias[col + 1]; v2 += bias[col + 2]; v3 += bias[col + 3];
    }
    uint2 ph;
    ph.x = pack2h(v0, v1); ph.y = pack2h(v2, v3);
    ((uint2*)dst)[idx] = ph;
}

// ---------------------------------------------------------------------------
// Causal softmax over row i (len = i+1); scores = (p0+p1)+(p2+p3);
// wh fp16 up to block-aligned limit; out += 0.25*w (full row).
// ---------------------------------------------------------------------------
__global__ __launch_bounds__(256) void softmax_causal_acc(
    const float* __restrict__ w0, const float* __restrict__ w1,
    const float* __restrict__ w2, const float* __restrict__ w3,
    __half* __restrict__ wh, float* __restrict__ out, int first)
{
    const int i = blockIdx.x;
    const int len = i + 1;
    const int limit = ((i >> 7) + 1) << 7;
    const int tid = threadIdx.x;

    __shared__ float row[NTOK];
    __shared__ float red[256];

    const float* wr0 = w0 + (size_t)i * NTOK;
    const float* wr1 = w1 + (size_t)i * NTOK;
    const float* wr2 = w2 + (size_t)i * NTOK;
    const float* wr3 = w3 + (size_t)i * NTOK;

    float m = -3.4e38f;
    for (int j = tid; j < len; j += 256) {
        float v = (wr0[j] + wr1[j]) + (wr2[j] + wr3[j]);
        row[j] = v;
        m = fmaxf(m, v);
    }
    red[tid] = m;
    __syncthreads();
#pragma unroll
    for (int s = 128; s > 0; s >>= 1) {
        if (tid < s) red[tid] = fmaxf(red[tid], red[tid + s]);
        __syncthreads();
    }
    m = red[0];
    __syncthreads();

    float sum = 0.f;
    for (int j = tid; j < len; j += 256) {
        float e = __expf(row[j] - m);
        row[j] = e;
        sum += e;
    }
    red[tid] = sum;
    __syncthreads();
#pragma unroll
    for (int s = 128; s > 0; s >>= 1) {
        if (tid < s) red[tid] += red[tid + s];
        __syncthreads();
    }
    const float inv = 1.0f / red[0];

    float* outr = out + (size_t)i * NTOK;
    __half* hr = wh + (size_t)i * NTOK;
    for (int j = tid; j < NTOK; j += 256) {
        float v = (j < len) ? row[j] * inv : 0.f;
        if (j < limit) hr[j] = __float2half_rn(v);
        if (first) outr[j] = 0.25f * v;
        else       outr[j] += 0.25f * v;
    }
}

// fp32 -> fp16 convert (vectorized by 4)
__global__ void conv_f16(const float* __restrict__ src,
                         __half* __restrict__ dst, int n4)
{
    int idx = blockIdx.x * blockDim.x + threadIdx.x;
    if (idx >= n4) return;
    float4 v = ((const float4*)src)[idx];
    uint2 ph;
    ph.x = pack2h(v.x, v.y); ph.y = pack2h(v.z, v.w);
    ((uint2*)dst)[idx] = ph;
}

// ---------------------------------------------------------------------------
extern "C" void kernel_launch(void* const* d_in, const int* in_sizes, int n_in,
                              void* d_out, int out_size)
{
    const float* mentions = (const float*)d_in[0];  // [2048,1024]
    const float* Wqkv     = (const float*)d_in[1];  // [4,3072,1024]
    const float* bqkv     = (const float*)d_in[2];  // [4,3072]
    const float* Wo       = (const float*)d_in[3];  // [4,1024,1024]
    const float* bo       = (const float*)d_in[4];  // [4,1024]
    float* out            = (float*)d_out;          // [2048,2048]

    __half *x, *qkv, *wh, *vT, *wv, *Wq, *Wl;
    float *p0, *p1, *p2, *p3, *sp0, *sp1, *sp2, *sp3;
    cudaGetSymbolAddress((void**)&x, g_x);
    cudaGetSymbolAddress((void**)&qkv, g_qkv);
    cudaGetSymbolAddress((void**)&p0, g_p0);   cudaGetSymbolAddress((void**)&p1, g_p1);
    cudaGetSymbolAddress((void**)&p2, g_p2);   cudaGetSymbolAddress((void**)&p3, g_p3);
    cudaGetSymbolAddress((void**)&sp0, g_sp0); cudaGetSymbolAddress((void**)&sp1, g_sp1);
    cudaGetSymbolAddress((void**)&sp2, g_sp2); cudaGetSymbolAddress((void**)&sp3, g_sp3);
    cudaGetSymbolAddress((void**)&wh, g_wh);
    cudaGetSymbolAddress((void**)&vT, g_vT);
    cudaGetSymbolAddress((void**)&wv, g_wv);
    cudaGetSymbolAddress((void**)&Wq, g_Wqkv);
    cudaGetSymbolAddress((void**)&Wl, g_Wo);

    cudaFuncSetAttribute(gemm_mma<2, false, false>,
                         cudaFuncAttributeMaxDynamicSharedMemorySize, SMEM_BYTES);
    cudaFuncSetAttribute(gemm_mma<4, true, false>,
                         cudaFuncAttributeMaxDynamicSharedMemorySize, SMEM_BYTES);
    cudaFuncSetAttribute(gemm_mma<4, false, true>,
                         cudaFuncAttributeMaxDynamicSharedMemorySize, SMEM_BYTES);

    const float scale = 1.0f / 32.0f;   // 1/sqrt(1024)

    // Convert weights + input activations to fp16
    {
        int n4 = NLAYER * 3 * EDIM * EDIM / 4;
        conv_f16<<<(n4 + 255) / 256, 256>>>(Wqkv, Wq, n4);
        n4 = NLAYER * EDIM * EDIM / 4;
        conv_f16<<<(n4 + 255) / 256, 256>>>(Wo, Wl, n4);
        n4 = NTOK * EDIM / 4;
        conv_f16<<<(n4 + 255) / 256, 256>>>(mentions, x, n4);
    }

    for (int l = 0; l < NLAYER; l++) {
        const __half* Wqh = Wq + (size_t)l * 3 * EDIM * EDIM;
        const __half* Woh = Wl + (size_t)l * EDIM * EDIM;
        const float* bq = bqkv + (size_t)l * 3 * EDIM;
        const float* bl = bo   + (size_t)l * EDIM;

        // qkv partials = x @ Wqkv^T   (split-K x2, 2.6 waves: balanced)
        gemm_mma<2, false, false><<<dim3(24, 16, 2), 256, SMEM_BYTES>>>(
            x, EDIM, Wqh, EDIM, p0, p1, p0, p1, 3 * EDIM, EDIM, 1.0f);
        // qkv = p0 + p1 + bqkv -> fp16, AND vT for the v slice (fused)
        combine_qkv_transpose<<<dim3(48, 32), 256>>>(p0, p1, bq, qkv, vT);

        // scores partials = scale * q @ k^T  (split-K x4 -> 2 CTAs/SM)
        gemm_mma<4, true, false><<<dim3(16, 16, 4), 256, SMEM_BYTES>>>(
            qkv, 3 * EDIM, qkv + EDIM, 3 * EDIM, p0, p1, p2, p3, NTOK,
            EDIM, scale);

        // softmax (sums 4 partials) -> wh fp16 + out accumulation
        softmax_causal_acc<<<NTOK, 256>>>(p0, p1, p2, p3, wh, out,
                                          l == 0 ? 1 : 0);

        // wv partials = w @ v  (split-K x4: balances the KLIM wave)
        gemm_mma<4, false, true><<<dim3(8, 16, 4), 256, SMEM_BYTES>>>(
            wh, NTOK, vT, NTOK, sp0, sp1, sp2, sp3, EDIM, NTOK, 1.0f);
        combine_split4<<<(NTOK * EDIM / 4 + 255) / 256, 256>>>(
            sp0, sp1, sp2, sp3, nullptr, wv, EDIM, NTOK * EDIM / 4);

        // x partials = wv @ Wo^T  (split-K x2, balanced single wave)
        gemm_mma<2, false, false><<<dim3(8, 16, 2), 256, SMEM_BYTES>>>(
            wv, EDIM, Woh, EDIM, sp0, sp1, sp0, sp1, EDIM, EDIM, 1.0f);
        combine_split<<<(NTOK * EDIM / 4 + 255) / 256, 256>>>(
            sp0, sp1, bl, x, EDIM, NTOK * EDIM / 4);
    }
}

// round 14
// speedup vs baseline: 1.0448x; 1.0448x over previous
#include <cuda_runtime.h>
#include <cuda_fp16.h>
#include <stdint.h>
#include <math.h>

#define NTOK 2048
#define EDIM 1024
#define NLAYER 4

// ---------------------------------------------------------------------------
// Scratch (device globals — allocation is forbidden). Pure fp16 operands.
// ---------------------------------------------------------------------------
__device__ __half g_x[NTOK * EDIM];
__device__ __half g_qkv[NTOK * 3 * EDIM];
__device__ float  g_p0[NTOK * 3 * EDIM];   // qkv / scores partials (x2)
__device__ float  g_p1[NTOK * 3 * EDIM];
__device__ float  g_sp0[NTOK * EDIM];      // wv(x4) / out-proj(x2) partials
__device__ float  g_sp1[NTOK * EDIM];
__device__ float  g_sp2[NTOK * EDIM];
__device__ float  g_sp3[NTOK * EDIM];
__device__ __half g_wh[NTOK * NTOK];
__device__ __half g_vT[EDIM * NTOK];
__device__ __half g_wv[NTOK * EDIM];
__device__ __half g_Wqkv[NLAYER * 3 * EDIM * EDIM];
__device__ __half g_Wo[NLAYER * EDIM * EDIM];

// ---------------------------------------------------------------------------
// Helpers
// ---------------------------------------------------------------------------
__device__ __forceinline__ uint32_t s2u(const void* p) {
    uint32_t a;
    asm("{ .reg .u64 t; cvta.to.shared.u64 t, %1; cvt.u32.u64 %0, t; }" : "=r"(a) : "l"(p));
    return a;
}
#define CPA(sm, gp) \
    asm volatile("cp.async.cg.shared.global [%0], [%1], 16;" :: "r"(sm), "l"(gp))
#define CPA_COMMIT() asm volatile("cp.async.commit_group;")
#define CPA_WAIT2()  asm volatile("cp.async.wait_group 2;")

#define LDSM4(r0, r1, r2, r3, addr)                                          \
    asm volatile("ldmatrix.sync.aligned.m8n8.x4.shared.b16 {%0,%1,%2,%3}, [%4];" \
                 : "=r"(r0), "=r"(r1), "=r"(r2), "=r"(r3) : "r"(addr))

__device__ __forceinline__ void mma16816(float* c, const uint32_t* a, const uint32_t* b) {
    asm volatile(
        "mma.sync.aligned.m16n8k16.row.col.f32.f16.f16.f32 "
        "{%0,%1,%2,%3}, {%4,%5,%6,%7}, {%8,%9}, {%0,%1,%2,%3};"
        : "+f"(c[0]), "+f"(c[1]), "+f"(c[2]), "+f"(c[3])
        : "r"(a[0]), "r"(a[1]), "r"(a[2]), "r"(a[3]), "r"(b[0]), "r"(b[1]));
}

__device__ __forceinline__ uint32_t pack2h(float a, float b) {
    __half2 t = __floats2half2_rn(a, b);
    return *reinterpret_cast<uint32_t*>(&t);
}

// SMEM: 4 stages; stage = 2 tiles (A, B) of 128 rows x 16 fp16, 48B pitch.
// (R8 mainloop configuration: best measured. DO NOT TOUCH.)
#define TILE_B   6144          // 128 * 48
#define STAGE_B  12288         // 2 tiles
#define SMEM_BYTES (4 * STAGE_B)   // 49152

// ---------------------------------------------------------------------------
// Split-K (xNSPLIT) tensor-core NT GEMM, single-pass fp16 (R8 mainloop):
//   partial[kz] = sum_{k in slice kz} A*B^T   (fp32 out)
//   CSKIP: skip blocks strictly above diagonal;  KLIM: Keff = (by+1)*128
// 4-stage cp.async pipeline, ONE __syncthreads per K=16 chunk.
// Prologue guarded (supports nch >= 2).
// ---------------------------------------------------------------------------
template<int NSPLIT, bool CSKIP, bool KLIM>
__global__ void __launch_bounds__(256, 2) gemm_mma(
    const __half* __restrict__ A, int lda,
    const __half* __restrict__ B, int ldb,
    float* __restrict__ Cf0, float* __restrict__ Cf1,
    float* __restrict__ Cf2, float* __restrict__ Cf3, int ldc,
    int K, float alpha)
{
    const int bx = blockIdx.x, by = blockIdx.y, kz = blockIdx.z;
    if (CSKIP && bx > by) return;
    const int Keff  = KLIM ? min(K, (by + 1) * 128) : K;
    const int slice = Keff / NSPLIT;       // multiple of 32
    const int k0    = kz * slice;
    const int nch   = slice / 16;          // >= 2 in all uses

    float* __restrict__ Cp = (kz == 0) ? Cf0 : (kz == 1) ? Cf1
                           : (kz == 2) ? Cf2 : Cf3;

    extern __shared__ __align__(128) char smem[];
    const uint32_t sb = s2u(smem);

    const int tid  = threadIdx.x;
    const int wid  = tid >> 5, lane = tid & 31;
    const int wm   = (wid & 1) * 64;
    const int wn   = (wid >> 1) * 32;

    const __half* Ab = A + (size_t)(by * 128) * lda;
    const __half* Bb = B + (size_t)(bx * 128) * ldb;

    const uint32_t a_row = lane & 15;
    const uint32_t a_k   = (lane >> 4) * 16;
    const uint32_t b_row = (lane & 7) + (lane >> 4) * 8;
    const uint32_t b_k   = ((lane >> 3) & 1) * 16;

    float acc[4][4][4];
#pragma unroll
    for (int i = 0; i < 4; i++)
#pragma unroll
        for (int j = 0; j < 4; j++)
#pragma unroll
            for (int r = 0; r < 4; r++) acc[i][j][r] = 0.f;

    const int lrow = tid >> 1;
    const int lc   = tid & 1;
    const uint32_t lso = (uint32_t)lrow * 48 + lc * 16;
    const size_t   lga = (size_t)lrow * lda + lc * 8;
    const size_t   lgb = (size_t)lrow * ldb + lc * 8;

    auto load_stage = [&](int stage, int kt) {
        uint32_t base = sb + (uint32_t)stage * STAGE_B + lso;
        CPA(base,          Ab + lga + kt);
        CPA(base + TILE_B, Bb + lgb + kt);
    };

    // guarded prologue: supports nch >= 2 (empty groups keep count uniform)
#pragma unroll
    for (int s = 0; s < 3; s++) {
        if (s < nch) load_stage(s, k0 + s * 16);
        CPA_COMMIT();
    }

    for (int c = 0; c < nch; c++) {
        CPA_WAIT2();
        __syncthreads();
        if (c + 3 < nch) load_stage((c + 3) & 3, k0 + (c + 3) * 16);
        CPA_COMMIT();

        const uint32_t base = sb + (uint32_t)(c & 3) * STAGE_B;

        uint32_t bf[8];
        {
            uint32_t bb = base + TILE_B + (wn + b_row) * 48 + b_k;
            LDSM4(bf[0], bf[1], bf[2], bf[3], bb);
            LDSM4(bf[4], bf[5], bf[6], bf[7], bb + 16 * 48);
        }
#pragma unroll
        for (int mf = 0; mf < 4; mf++) {
            uint32_t ah[4];
            uint32_t ab = base + (wm + mf * 16 + a_row) * 48 + a_k;
            LDSM4(ah[0], ah[1], ah[2], ah[3], ab);
#pragma unroll
            for (int nf = 0; nf < 4; nf++)
                mma16816(acc[mf][nf], ah, bf + nf * 2);
        }
    }

#pragma unroll
    for (int mf = 0; mf < 4; mf++) {
#pragma unroll
        for (int nf = 0; nf < 4; nf++) {
            const float* cc = acc[mf][nf];
            int row0 = by * 128 + wm + mf * 16 + (lane >> 2);
            int col  = bx * 128 + wn + nf * 8 + (lane & 3) * 2;
            float2 v0 = make_float2(alpha * cc[0], alpha * cc[1]);
            float2 v1 = make_float2(alpha * cc[2], alpha * cc[3]);
            *(float2*)(Cp + (size_t)row0 * ldc + col) = v0;
            *(float2*)(Cp + (size_t)(row0 + 8) * ldc + col) = v1;
        }
    }
}

// ---------------------------------------------------------------------------
// Fused qkv combine + v transpose (R11 kernel, unchanged; 2 partials).
// ---------------------------------------------------------------------------
__global__ __launch_bounds__(256) void combine_qkv_transpose(
    const float* __restrict__ p0, const float* __restrict__ p1,
    const float* __restrict__ bias,
    __half* __restrict__ qkv, __half* __restrict__ vT)
{
    __shared__ __half sh[64][65];
    const int c0 = blockIdx.x * 64, r0 = blockIdx.y * 64;
    const int tid = threadIdx.x;
    const int col4 = tid & 15;
    const int rbase = tid >> 4;
    const bool vtile = (c0 >= 2 * EDIM);

    float b0 = bias[c0 + col4 * 4 + 0];
    float b1 = bias[c0 + col4 * 4 + 1];
    float b2 = bias[c0 + col4 * 4 + 2];
    float b3 = bias[c0 + col4 * 4 + 3];

#pragma unroll
    for (int rr = 0; rr < 4; rr++) {
        int r = rbase + rr * 16;
        size_t idx4 = ((size_t)(r0 + r) * (3 * EDIM) + c0 + col4 * 4) >> 2;
        float4 a = ((const float4*)p0)[idx4];
        float4 b = ((const float4*)p1)[idx4];
        float v0 = a.x + b.x + b0, v1 = a.y + b.y + b1;
        float v2 = a.z + b.z + b2, v3 = a.w + b.w + b3;
        uint2 ph;
        ph.x = pack2h(v0, v1); ph.y = pack2h(v2, v3);
        ((uint2*)qkv)[idx4] = ph;
        if (vtile) {
            __half2 h01 = __floats2half2_rn(v0, v1);
            __half2 h23 = __floats2half2_rn(v2, v3);
            sh[r][col4 * 4 + 0] = __low2half(h01);
            sh[r][col4 * 4 + 1] = __high2half(h01);
            sh[r][col4 * 4 + 2] = __low2half(h23);
            sh[r][col4 * 4 + 3] = __high2half(h23);
        }
    }

    if (vtile) {
        __syncthreads();
        const int cc = tid & 63;
        const int rg = tid >> 6;
        __half tmp[16];
#pragma unroll
        for (int j = 0; j < 16; j++) tmp[j] = sh[rg * 16 + j][cc];
        size_t dst = (size_t)(c0 - 2 * EDIM + cc) * NTOK + r0 + rg * 16;
        *(uint4*)(vT + dst)     = *(uint4*)&tmp[0];
        *(uint4*)(vT + dst + 8) = *(uint4*)&tmp[8];
    }
}

// ---------------------------------------------------------------------------
// combine 4 split-K partials: v = (p0+p1)+(p2+p3) (+ bias); write fp16
// ---------------------------------------------------------------------------
__global__ void combine_split4(const float* __restrict__ p0, const float* __restrict__ p1,
                               const float* __restrict__ p2, const float* __restrict__ p3,
                               const float* __restrict__ bias,
                               __half* __restrict__ dst, int ncols, int n4)
{
    int idx = blockIdx.x * blockDim.x + threadIdx.x;
    if (idx >= n4) return;
    float4 a = ((const float4*)p0)[idx];
    float4 b = ((const float4*)p1)[idx];
    float4 c = ((const float4*)p2)[idx];
    float4 d = ((const float4*)p3)[idx];
    float v0 = (a.x + b.x) + (c.x + d.x);
    float v1 = (a.y + b.y) + (c.y + d.y);
    float v2 = (a.z + b.z) + (c.z + d.z);
    float v3 = (a.w + b.w) + (c.w + d.w);
    if (bias) {
        int col = (idx * 4) % ncols;
        v0 += bias[col]; v1 += bias[col + 1]; v2 += bias[col + 2]; v3 += bias[col + 3];
    }
    uint2 ph;
    ph.x = pack2h(v0, v1); ph.y = pack2h(v2, v3);
    ((uint2*)dst)[idx] = ph;
}

// combine 2 split-K partials (out-proj path)
__global__ void combine_split(const float* __restrict__ p0, const float* __restrict__ p1,
                              const float* __restrict__ bias,
                              __half* __restrict__ dst, int ncols, int n4)
{
    int idx = blockIdx.x * blockDim.x + threadIdx.x;
    if (idx >= n4) return;
    float4 a = ((const float4*)p0)[idx];
    float4 b = ((const float4*)p1)[idx];
    float v0 = a.x + b.x, v1 = a.y + b.y, v2 = a.z + b.z, v3 = a.w + b.w;
    if (bias) {
        int col = (idx * 4) % ncols;
        v0 += bias[col]; v1 += bias[col + 1]; v2 += bias[col + 2]; v3 += bias[col + 3];
    }
    uint2 ph;
    ph.x = pack2h(v0, v1); ph.y = pack2h(v2, v3);
    ((uint2*)dst)[idx] = ph;
}

// ---------------------------------------------------------------------------
// Causal softmax over row i (len = i+1); scores = p0 + p1 (2 partials);
// wh fp16 up to block-aligned limit; out accumulation:
//   first layer: full row (writes the zero upper triangle once)
//   later layers: j < len only (upper-triangle addends are exactly 0)
// ---------------------------------------------------------------------------
__global__ __launch_bounds__(256) void softmax_causal_acc(
    const float* __restrict__ w0, const float* __restrict__ w1,
    __half* __restrict__ wh, float* __restrict__ out, int first)
{
    const int i = blockIdx.x;
    const int len = i + 1;
    const int limit = ((i >> 7) + 1) << 7;
    const int tid = threadIdx.x;

    __shared__ float row[NTOK];
    __shared__ float red[256];

    const float* wr0 = w0 + (size_t)i * NTOK;
    const float* wr1 = w1 + (size_t)i * NTOK;

    float m = -3.4e38f;
    for (int j = tid; j < len; j += 256) {
        float v = wr0[j] + wr1[j];
        row[j] = v;
        m = fmaxf(m, v);
    }
    red[tid] = m;
    __syncthreads();
#pragma unroll
    for (int s = 128; s > 0; s >>= 1) {
        if (tid < s) red[tid] = fmaxf(red[tid], red[tid + s]);
        __syncthreads();
    }
    m = red[0];
    __syncthreads();

    float sum = 0.f;
    for (int j = tid; j < len; j += 256) {
        float e = __expf(row[j] - m);   // arg <= 0, bounded
        row[j] = e;
        sum += e;
    }
    red[tid] = sum;
    __syncthreads();
#pragma unroll
    for (int s = 128; s > 0; s >>= 1) {
        if (tid < s) red[tid] += red[tid + s];
        __syncthreads();
    }
    const float inv = 1.0f / red[0];

    float* outr = out + (size_t)i * NTOK;
    __half* hr = wh + (size_t)i * NTOK;
    for (int j = tid; j < limit; j += 256) {
        float v = (j < len) ? row[j] * inv : 0.f;
        hr[j] = __float2half_rn(v);
    }
    if (first) {
        for (int j = tid; j < NTOK; j += 256) {
            float v = (j < len) ? row[j] * inv : 0.f;
            outr[j] = 0.25f * v;
        }
    } else {
        for (int j = tid; j < len; j += 256)
            outr[j] += 0.25f * (row[j] * inv);
    }
}

// fp32 -> fp16 convert (vectorized by 4)
__global__ void conv_f16(const float* __restrict__ src,
                         __half* __restrict__ dst, int n4)
{
    int idx = blockIdx.x * blockDim.x + threadIdx.x;
    if (idx >= n4) return;
    float4 v = ((const float4*)src)[idx];
    uint2 ph;
    ph.x = pack2h(v.x, v.y); ph.y = pack2h(v.z, v.w);
    ((uint2*)dst)[idx] = ph;
}

// ---------------------------------------------------------------------------
extern "C" void kernel_launch(void* const* d_in, const int* in_sizes, int n_in,
                              void* d_out, int out_size)
{
    const float* mentions = (const float*)d_in[0];  // [2048,1024]
    const float* Wqkv     = (const float*)d_in[1];  // [4,3072,1024]
    const float* bqkv     = (const float*)d_in[2];  // [4,3072]
    const float* Wo       = (const float*)d_in[3];  // [4,1024,1024]
    const float* bo       = (const float*)d_in[4];  // [4,1024]
    float* out            = (float*)d_out;          // [2048,2048]

    __half *x, *qkv, *wh, *vT, *wv, *Wq, *Wl;
    float *p0, *p1, *sp0, *sp1, *sp2, *sp3;
    cudaGetSymbolAddress((void**)&x, g_x);
    cudaGetSymbolAddress((void**)&qkv, g_qkv);
    cudaGetSymbolAddress((void**)&p0, g_p0);   cudaGetSymbolAddress((void**)&p1, g_p1);
    cudaGetSymbolAddress((void**)&sp0, g_sp0); cudaGetSymbolAddress((void**)&sp1, g_sp1);
    cudaGetSymbolAddress((void**)&sp2, g_sp2); cudaGetSymbolAddress((void**)&sp3, g_sp3);
    cudaGetSymbolAddress((void**)&wh, g_wh);
    cudaGetSymbolAddress((void**)&vT, g_vT);
    cudaGetSymbolAddress((void**)&wv, g_wv);
    cudaGetSymbolAddress((void**)&Wq, g_Wqkv);
    cudaGetSymbolAddress((void**)&Wl, g_Wo);

    cudaFuncSetAttribute(gemm_mma<2, false, false>,
                         cudaFuncAttributeMaxDynamicSharedMemorySize, SMEM_BYTES);
    cudaFuncSetAttribute(gemm_mma<2, true, false>,
                         cudaFuncAttributeMaxDynamicSharedMemorySize, SMEM_BYTES);
    cudaFuncSetAttribute(gemm_mma<4, false, true>,
                         cudaFuncAttributeMaxDynamicSharedMemorySize, SMEM_BYTES);

    const float scale = 1.0f / 32.0f;   // 1/sqrt(1024)

    // Convert weights + input activations to fp16
    {
        int n4 = NLAYER * 3 * EDIM * EDIM / 4;
        conv_f16<<<(n4 + 255) / 256, 256>>>(Wqkv, Wq, n4);
        n4 = NLAYER * EDIM * EDIM / 4;
        conv_f16<<<(n4 + 255) / 256, 256>>>(Wo, Wl, n4);
        n4 = NTOK * EDIM / 4;
        conv_f16<<<(n4 + 255) / 256, 256>>>(mentions, x, n4);
    }

    for (int l = 0; l < NLAYER; l++) {
        const __half* Wqh = Wq + (size_t)l * 3 * EDIM * EDIM;
        const __half* Woh = Wl + (size_t)l * EDIM * EDIM;
        const float* bq = bqkv + (size_t)l * 3 * EDIM;
        const float* bl = bo   + (size_t)l * EDIM;

        // qkv partials = x @ Wqkv^T   (split-K x2, 2.6 waves: balanced)
        gemm_mma<2, false, false><<<dim3(24, 16, 2), 256, SMEM_BYTES>>>(
            x, EDIM, Wqh, EDIM, p0, p1, p0, p1, 3 * EDIM, EDIM, 1.0f);
        // qkv = p0 + p1 + bqkv -> fp16, AND vT for the v slice (fused)
        combine_qkv_transpose<<<dim3(48, 32), 256>>>(p0, p1, bq, qkv, vT);

        // scores partials = scale * q @ k^T  (split-K x2, lower blocks only)
        gemm_mma<2, true, false><<<dim3(16, 16, 2), 256, SMEM_BYTES>>>(
            qkv, 3 * EDIM, qkv + EDIM, 3 * EDIM, p0, p1, p0, p1, NTOK,
            EDIM, scale);

        // softmax (2 partials) -> wh fp16 + out accumulation (len-trimmed)
        softmax_causal_acc<<<NTOK, 256>>>(p0, p1, wh, out, l == 0 ? 1 : 0);

        // wv partials = w @ v  (split-K x4: balances the KLIM single wave)
        gemm_mma<4, false, true><<<dim3(8, 16, 4), 256, SMEM_BYTES>>>(
            wh, NTOK, vT, NTOK, sp0, sp1, sp2, sp3, EDIM, NTOK, 1.0f);
        combine_split4<<<(NTOK * EDIM / 4 + 255) / 256, 256>>>(
            sp0, sp1, sp2, sp3, nullptr, wv, EDIM, NTOK * EDIM / 4);

        // x partials = wv @ Wo^T  (split-K x2, balanced single wave)
        gemm_mma<2, false, false><<<dim3(8, 16, 2), 256, SMEM_BYTES>>>(
            wv, EDIM, Woh, EDIM, sp0, sp1, sp0, sp1, EDIM, EDIM, 1.0f);
        combine_split<<<(NTOK * EDIM / 4 + 255) / 256, 256>>>(
            sp0, sp1, bl, x, EDIM, NTOK * EDIM / 4);
    }
}

// round 15
// speedup vs baseline: 1.1934x; 1.1423x over previous
#include <cuda_runtime.h>
#include <cuda_fp16.h>
#include <stdint.h>
#include <math.h>

#define NTOK 2048
#define EDIM 1024
#define NLAYER 4

// ---------------------------------------------------------------------------
// Scratch (device globals — allocation is forbidden). Pure fp16 operands.
// ---------------------------------------------------------------------------
__device__ __half g_x[NTOK * EDIM];
__device__ __half g_qkv[NTOK * 3 * EDIM];
__device__ float  g_p0[NTOK * 3 * EDIM];   // qkv / scores partials (x2)
__device__ float  g_p1[NTOK * 3 * EDIM];
__device__ float  g_sp0[NTOK * EDIM];      // wv(x4) / out-proj(x2) partials
__device__ float  g_sp1[NTOK * EDIM];
__device__ float  g_sp2[NTOK * EDIM];
__device__ float  g_sp3[NTOK * EDIM];
__device__ __half g_wh[NTOK * NTOK];
__device__ __half g_vT[EDIM * NTOK];
__device__ __half g_wv[NTOK * EDIM];
__device__ __half g_Wqkv[NLAYER * 3 * EDIM * EDIM];
__device__ __half g_Wo[NLAYER * EDIM * EDIM];

// ---------------------------------------------------------------------------
// Helpers
// ---------------------------------------------------------------------------
__device__ __forceinline__ uint32_t s2u(const void* p) {
    uint32_t a;
    asm("{ .reg .u64 t; cvta.to.shared.u64 t, %1; cvt.u32.u64 %0, t; }" : "=r"(a) : "l"(p));
    return a;
}
#define CPA(sm, gp) \
    asm volatile("cp.async.cg.shared.global [%0], [%1], 16;" :: "r"(sm), "l"(gp))
#define CPA_COMMIT() asm volatile("cp.async.commit_group;")
#define CPA_WAIT2()  asm volatile("cp.async.wait_group 2;")

#define LDSM4(r0, r1, r2, r3, addr)                                          \
    asm volatile("ldmatrix.sync.aligned.m8n8.x4.shared.b16 {%0,%1,%2,%3}, [%4];" \
                 : "=r"(r0), "=r"(r1), "=r"(r2), "=r"(r3) : "r"(addr))

__device__ __forceinline__ void mma16816(float* c, const uint32_t* a, const uint32_t* b) {
    asm volatile(
        "mma.sync.aligned.m16n8k16.row.col.f32.f16.f16.f32 "
        "{%0,%1,%2,%3}, {%4,%5,%6,%7}, {%8,%9}, {%0,%1,%2,%3};"
        : "+f"(c[0]), "+f"(c[1]), "+f"(c[2]), "+f"(c[3])
        : "r"(a[0]), "r"(a[1]), "r"(a[2]), "r"(a[3]), "r"(b[0]), "r"(b[1]));
}

__device__ __forceinline__ uint32_t pack2h(float a, float b) {
    __half2 t = __floats2half2_rn(a, b);
    return *reinterpret_cast<uint32_t*>(&t);
}

// SMEM: 4 stages; stage = 2 tiles (A, B) of 128 rows x 16 fp16, 48B pitch.
// (R8 mainloop configuration: best measured. DO NOT TOUCH.)
#define TILE_B   6144          // 128 * 48
#define STAGE_B  12288         // 2 tiles
#define SMEM_BYTES (4 * STAGE_B)   // 49152

// ---------------------------------------------------------------------------
// Split-K (xNSPLIT) tensor-core NT GEMM, single-pass fp16 (R8 mainloop):
//   partial[kz] = sum_{k in slice kz} A*B^T   (fp32 out)
//   CSKIP: skip blocks strictly above diagonal;  KLIM: Keff = (by+1)*128
// 4-stage cp.async pipeline, ONE __syncthreads per K=16 chunk.
// Prologue guarded (supports nch >= 2).
// ---------------------------------------------------------------------------
template<int NSPLIT, bool CSKIP, bool KLIM>
__global__ void __launch_bounds__(256, 2) gemm_mma(
    const __half* __restrict__ A, int lda,
    const __half* __restrict__ B, int ldb,
    float* __restrict__ Cf0, float* __restrict__ Cf1,
    float* __restrict__ Cf2, float* __restrict__ Cf3, int ldc,
    int K, float alpha)
{
    const int bx = blockIdx.x, by = blockIdx.y, kz = blockIdx.z;
    if (CSKIP && bx > by) return;
    const int Keff  = KLIM ? min(K, (by + 1) * 128) : K;
    const int slice = Keff / NSPLIT;       // multiple of 32
    const int k0    = kz * slice;
    const int nch   = slice / 16;          // >= 2 in all uses

    float* __restrict__ Cp = (kz == 0) ? Cf0 : (kz == 1) ? Cf1
                           : (kz == 2) ? Cf2 : Cf3;

    extern __shared__ __align__(128) char smem[];
    const uint32_t sb = s2u(smem);

    const int tid  = threadIdx.x;
    const int wid  = tid >> 5, lane = tid & 31;
    const int wm   = (wid & 1) * 64;
    const int wn   = (wid >> 1) * 32;

    const __half* Ab = A + (size_t)(by * 128) * lda;
    const __half* Bb = B + (size_t)(bx * 128) * ldb;

    const uint32_t a_row = lane & 15;
    const uint32_t a_k   = (lane >> 4) * 16;
    const uint32_t b_row = (lane & 7) + (lane >> 4) * 8;
    const uint32_t b_k   = ((lane >> 3) & 1) * 16;

    float acc[4][4][4];
#pragma unroll
    for (int i = 0; i < 4; i++)
#pragma unroll
        for (int j = 0; j < 4; j++)
#pragma unroll
            for (int r = 0; r < 4; r++) acc[i][j][r] = 0.f;

    const int lrow = tid >> 1;
    const int lc   = tid & 1;
    const uint32_t lso = (uint32_t)lrow * 48 + lc * 16;
    const size_t   lga = (size_t)lrow * lda + lc * 8;
    const size_t   lgb = (size_t)lrow * ldb + lc * 8;

    auto load_stage = [&](int stage, int kt) {
        uint32_t base = sb + (uint32_t)stage * STAGE_B + lso;
        CPA(base,          Ab + lga + kt);
        CPA(base + TILE_B, Bb + lgb + kt);
    };

    // guarded prologue: supports nch >= 2 (empty groups keep count uniform)
#pragma unroll
    for (int s = 0; s < 3; s++) {
        if (s < nch) load_stage(s, k0 + s * 16);
        CPA_COMMIT();
    }

    for (int c = 0; c < nch; c++) {
        CPA_WAIT2();
        __syncthreads();
        if (c + 3 < nch) load_stage((c + 3) & 3, k0 + (c + 3) * 16);
        CPA_COMMIT();

        const uint32_t base = sb + (uint32_t)(c & 3) * STAGE_B;

        uint32_t bf[8];
        {
            uint32_t bb = base + TILE_B + (wn + b_row) * 48 + b_k;
            LDSM4(bf[0], bf[1], bf[2], bf[3], bb);
            LDSM4(bf[4], bf[5], bf[6], bf[7], bb + 16 * 48);
        }
#pragma unroll
        for (int mf = 0; mf < 4; mf++) {
            uint32_t ah[4];
            uint32_t ab = base + (wm + mf * 16 + a_row) * 48 + a_k;
            LDSM4(ah[0], ah[1], ah[2], ah[3], ab);
#pragma unroll
            for (int nf = 0; nf < 4; nf++)
                mma16816(acc[mf][nf], ah, bf + nf * 2);
        }
    }

#pragma unroll
    for (int mf = 0; mf < 4; mf++) {
#pragma unroll
        for (int nf = 0; nf < 4; nf++) {
            const float* cc = acc[mf][nf];
            int row0 = by * 128 + wm + mf * 16 + (lane >> 2);
            int col  = bx * 128 + wn + nf * 8 + (lane & 3) * 2;
            float2 v0 = make_float2(alpha * cc[0], alpha * cc[1]);
            float2 v1 = make_float2(alpha * cc[2], alpha * cc[3]);
            *(float2*)(Cp + (size_t)row0 * ldc + col) = v0;
            *(float2*)(Cp + (size_t)(row0 + 8) * ldc + col) = v1;
        }
    }
}

// ---------------------------------------------------------------------------
// Fused qkv combine + v transpose (R11 kernel; grid.x=48 full, 32 = q,k only).
// ---------------------------------------------------------------------------
__global__ __launch_bounds__(256) void combine_qkv_transpose(
    const float* __restrict__ p0, const float* __restrict__ p1,
    const float* __restrict__ bias,
    __half* __restrict__ qkv, __half* __restrict__ vT)
{
    __shared__ __half sh[64][65];
    const int c0 = blockIdx.x * 64, r0 = blockIdx.y * 64;
    const int tid = threadIdx.x;
    const int col4 = tid & 15;
    const int rbase = tid >> 4;
    const bool vtile = (c0 >= 2 * EDIM);

    float b0 = bias[c0 + col4 * 4 + 0];
    float b1 = bias[c0 + col4 * 4 + 1];
    float b2 = bias[c0 + col4 * 4 + 2];
    float b3 = bias[c0 + col4 * 4 + 3];

#pragma unroll
    for (int rr = 0; rr < 4; rr++) {
        int r = rbase + rr * 16;
        size_t idx4 = ((size_t)(r0 + r) * (3 * EDIM) + c0 + col4 * 4) >> 2;
        float4 a = ((const float4*)p0)[idx4];
        float4 b = ((const float4*)p1)[idx4];
        float v0 = a.x + b.x + b0, v1 = a.y + b.y + b1;
        float v2 = a.z + b.z + b2, v3 = a.w + b.w + b3;
        uint2 ph;
        ph.x = pack2h(v0, v1); ph.y = pack2h(v2, v3);
        ((uint2*)qkv)[idx4] = ph;
        if (vtile) {
            __half2 h01 = __floats2half2_rn(v0, v1);
            __half2 h23 = __floats2half2_rn(v2, v3);
            sh[r][col4 * 4 + 0] = __low2half(h01);
            sh[r][col4 * 4 + 1] = __high2half(h01);
            sh[r][col4 * 4 + 2] = __low2half(h23);
            sh[r][col4 * 4 + 3] = __high2half(h23);
        }
    }

    if (vtile) {
        __syncthreads();
        const int cc = tid & 63;
        const int rg = tid >> 6;
        __half tmp[16];
#pragma unroll
        for (int j = 0; j < 16; j++) tmp[j] = sh[rg * 16 + j][cc];
        size_t dst = (size_t)(c0 - 2 * EDIM + cc) * NTOK + r0 + rg * 16;
        *(uint4*)(vT + dst)     = *(uint4*)&tmp[0];
        *(uint4*)(vT + dst + 8) = *(uint4*)&tmp[8];
    }
}

// ---------------------------------------------------------------------------
// combine 4 split-K partials: v = (p0+p1)+(p2+p3) (+ bias); write fp16
// ---------------------------------------------------------------------------
__global__ void combine_split4(const float* __restrict__ p0, const float* __restrict__ p1,
                               const float* __restrict__ p2, const float* __restrict__ p3,
                               const float* __restrict__ bias,
                               __half* __restrict__ dst, int ncols, int n4)
{
    int idx = blockIdx.x * blockDim.x + threadIdx.x;
    if (idx >= n4) return;
    float4 a = ((const float4*)p0)[idx];
    float4 b = ((const float4*)p1)[idx];
    float4 c = ((const float4*)p2)[idx];
    float4 d = ((const float4*)p3)[idx];
    float v0 = (a.x + b.x) + (c.x + d.x);
    float v1 = (a.y + b.y) + (c.y + d.y);
    float v2 = (a.z + b.z) + (c.z + d.z);
    float v3 = (a.w + b.w) + (c.w + d.w);
    if (bias) {
        int col = (idx * 4) % ncols;
        v0 += bias[col]; v1 += bias[col + 1]; v2 += bias[col + 2]; v3 += bias[col + 3];
    }
    uint2 ph;
    ph.x = pack2h(v0, v1); ph.y = pack2h(v2, v3);
    ((uint2*)dst)[idx] = ph;
}

// combine 2 split-K partials (out-proj path)
__global__ void combine_split(const float* __restrict__ p0, const float* __restrict__ p1,
                              const float* __restrict__ bias,
                              __half* __restrict__ dst, int ncols, int n4)
{
    int idx = blockIdx.x * blockDim.x + threadIdx.x;
    if (idx >= n4) return;
    float4 a = ((const float4*)p0)[idx];
    float4 b = ((const float4*)p1)[idx];
    float v0 = a.x + b.x, v1 = a.y + b.y, v2 = a.z + b.z, v3 = a.w + b.w;
    if (bias) {
        int col = (idx * 4) % ncols;
        v0 += bias[col]; v1 += bias[col + 1]; v2 += bias[col + 2]; v3 += bias[col + 3];
    }
    uint2 ph;
    ph.x = pack2h(v0, v1); ph.y = pack2h(v2, v3);
    ((uint2*)dst)[idx] = ph;
}

// ---------------------------------------------------------------------------
// Causal softmax over row i (len = i+1); scores = p0 + p1 (2 partials);
// wh fp16 written only when write_wh (last layer's weights feed nothing);
// out accumulation: first layer full row, later layers j < len only.
// ---------------------------------------------------------------------------
__global__ __launch_bounds__(256) void softmax_causal_acc(
    const float* __restrict__ w0, const float* __restrict__ w1,
    __half* __restrict__ wh, float* __restrict__ out, int first, int write_wh)
{
    const int i = blockIdx.x;
    const int len = i + 1;
    const int limit = ((i >> 7) + 1) << 7;
    const int tid = threadIdx.x;

    __shared__ float row[NTOK];
    __shared__ float red[256];

    const float* wr0 = w0 + (size_t)i * NTOK;
    const float* wr1 = w1 + (size_t)i * NTOK;

    float m = -3.4e38f;
    for (int j = tid; j < len; j += 256) {
        float v = wr0[j] + wr1[j];
        row[j] = v;
        m = fmaxf(m, v);
    }
    red[tid] = m;
    __syncthreads();
#pragma unroll
    for (int s = 128; s > 0; s >>= 1) {
        if (tid < s) red[tid] = fmaxf(red[tid], red[tid + s]);
        __syncthreads();
    }
    m = red[0];
    __syncthreads();

    float sum = 0.f;
    for (int j = tid; j < len; j += 256) {
        float e = __expf(row[j] - m);   // arg <= 0, bounded
        row[j] = e;
        sum += e;
    }
    red[tid] = sum;
    __syncthreads();
#pragma unroll
    for (int s = 128; s > 0; s >>= 1) {
        if (tid < s) red[tid] += red[tid + s];
        __syncthreads();
    }
    const float inv = 1.0f / red[0];

    float* outr = out + (size_t)i * NTOK;
    if (write_wh) {
        __half* hr = wh + (size_t)i * NTOK;
        for (int j = tid; j < limit; j += 256) {
            float v = (j < len) ? row[j] * inv : 0.f;
            hr[j] = __float2half_rn(v);
        }
    }
    if (first) {
        for (int j = tid; j < NTOK; j += 256) {
            float v = (j < len) ? row[j] * inv : 0.f;
            outr[j] = 0.25f * v;
        }
    } else {
        for (int j = tid; j < len; j += 256)
            outr[j] += 0.25f * (row[j] * inv);
    }
}

// fp32 -> fp16 convert (vectorized by 4)
__global__ void conv_f16(const float* __restrict__ src,
                         __half* __restrict__ dst, int n4)
{
    int idx = blockIdx.x * blockDim.x + threadIdx.x;
    if (idx >= n4) return;
    float4 v = ((const float4*)src)[idx];
    uint2 ph;
    ph.x = pack2h(v.x, v.y); ph.y = pack2h(v.z, v.w);
    ((uint2*)dst)[idx] = ph;
}

// ---------------------------------------------------------------------------
extern "C" void kernel_launch(void* const* d_in, const int* in_sizes, int n_in,
                              void* d_out, int out_size)
{
    const float* mentions = (const float*)d_in[0];  // [2048,1024]
    const float* Wqkv     = (const float*)d_in[1];  // [4,3072,1024]
    const float* bqkv     = (const float*)d_in[2];  // [4,3072]
    const float* Wo       = (const float*)d_in[3];  // [4,1024,1024]
    const float* bo       = (const float*)d_in[4];  // [4,1024]
    float* out            = (float*)d_out;          // [2048,2048]

    __half *x, *qkv, *wh, *vT, *wv, *Wq, *Wl;
    float *p0, *p1, *sp0, *sp1, *sp2, *sp3;
    cudaGetSymbolAddress((void**)&x, g_x);
    cudaGetSymbolAddress((void**)&qkv, g_qkv);
    cudaGetSymbolAddress((void**)&p0, g_p0);   cudaGetSymbolAddress((void**)&p1, g_p1);
    cudaGetSymbolAddress((void**)&sp0, g_sp0); cudaGetSymbolAddress((void**)&sp1, g_sp1);
    cudaGetSymbolAddress((void**)&sp2, g_sp2); cudaGetSymbolAddress((void**)&sp3, g_sp3);
    cudaGetSymbolAddress((void**)&wh, g_wh);
    cudaGetSymbolAddress((void**)&vT, g_vT);
    cudaGetSymbolAddress((void**)&wv, g_wv);
    cudaGetSymbolAddress((void**)&Wq, g_Wqkv);
    cudaGetSymbolAddress((void**)&Wl, g_Wo);

    cudaFuncSetAttribute(gemm_mma<2, false, false>,
                         cudaFuncAttributeMaxDynamicSharedMemorySize, SMEM_BYTES);
    cudaFuncSetAttribute(gemm_mma<2, true, false>,
                         cudaFuncAttributeMaxDynamicSharedMemorySize, SMEM_BYTES);
    cudaFuncSetAttribute(gemm_mma<4, false, true>,
                         cudaFuncAttributeMaxDynamicSharedMemorySize, SMEM_BYTES);

    const float scale = 1.0f / 32.0f;   // 1/sqrt(1024)

    // Convert weights + input activations to fp16 (layer-3 Wo never used ->
    // convert only layers 0..2 of Wo).
    {
        int n4 = NLAYER * 3 * EDIM * EDIM / 4;
        conv_f16<<<(n4 + 255) / 256, 256>>>(Wqkv, Wq, n4);
        n4 = (NLAYER - 1) * EDIM * EDIM / 4;
        conv_f16<<<(n4 + 255) / 256, 256>>>(Wo, Wl, n4);
        n4 = NTOK * EDIM / 4;
        conv_f16<<<(n4 + 255) / 256, 256>>>(mentions, x, n4);
    }

    for (int l = 0; l < NLAYER; l++) {
        const bool last = (l == NLAYER - 1);
        const __half* Wqh = Wq + (size_t)l * 3 * EDIM * EDIM;
        const __half* Woh = Wl + (size_t)l * EDIM * EDIM;
        const float* bq = bqkv + (size_t)l * 3 * EDIM;
        const float* bl = bo   + (size_t)l * EDIM;

        // qkv partials = x @ Wqkv^T (split-K x2). Last layer: q,k cols only.
        gemm_mma<2, false, false><<<dim3(last ? 16 : 24, 16, 2), 256, SMEM_BYTES>>>(
            x, EDIM, Wqh, EDIM, p0, p1, p0, p1, 3 * EDIM, EDIM, 1.0f);
        // qkv = p0 + p1 + bqkv -> fp16 (+ vT on non-last layers)
        combine_qkv_transpose<<<dim3(last ? 32 : 48, 32), 256>>>(p0, p1, bq, qkv, vT);

        // scores partials = scale * q @ k^T  (split-K x2, lower blocks only)
        gemm_mma<2, true, false><<<dim3(16, 16, 2), 256, SMEM_BYTES>>>(
            qkv, 3 * EDIM, qkv + EDIM, 3 * EDIM, p0, p1, p0, p1, NTOK,
            EDIM, scale);

        // softmax -> out accumulation (+ wh fp16 on non-last layers)
        softmax_causal_acc<<<NTOK, 256>>>(p0, p1, wh, out,
                                          l == 0 ? 1 : 0, last ? 0 : 1);

        if (last) break;   // wv / out-proj / x are dead beyond this point

        // wv partials = w @ v  (split-K x4: balances the KLIM single wave)
        gemm_mma<4, false, true><<<dim3(8, 16, 4), 256, SMEM_BYTES>>>(
            wh, NTOK, vT, NTOK, sp0, sp1, sp2, sp3, EDIM, NTOK, 1.0f);
        combine_split4<<<(NTOK * EDIM / 4 + 255) / 256, 256>>>(
            sp0, sp1, sp2, sp3, nullptr, wv, EDIM, NTOK * EDIM / 4);

        // x partials = wv @ Wo^T  (split-K x2, balanced single wave)
        gemm_mma<2, false, false><<<dim3(8, 16, 2), 256, SMEM_BYTES>>>(
            wv, EDIM, Woh, EDIM, sp0, sp1, sp0, sp1, EDIM, EDIM, 1.0f);
        combine_split<<<(NTOK * EDIM / 4 + 255) / 256, 256>>>(
            sp0, sp1, bl, x, EDIM, NTOK * EDIM / 4);
    }
}

// round 16
// speedup vs baseline: 1.2057x; 1.0103x over previous
#include <cuda_runtime.h>
#include <cuda_fp16.h>
#include <stdint.h>
#include <math.h>

#define NTOK 2048
#define EDIM 1024
#define NLAYER 4

// ---------------------------------------------------------------------------
// Scratch (device globals — allocation is forbidden). Pure fp16 operands.
// ---------------------------------------------------------------------------
__device__ __half g_x[NTOK * EDIM];
__device__ __half g_qkv[NTOK * 3 * EDIM];
__device__ float  g_p0[NTOK * 3 * EDIM];   // qkv / scores partials (x2)
__device__ float  g_p1[NTOK * 3 * EDIM];
__device__ float  g_sp0[NTOK * EDIM];      // wv(x4) / out-proj(x2) partials
__device__ float  g_sp1[NTOK * EDIM];
__device__ float  g_sp2[NTOK * EDIM];
__device__ float  g_sp3[NTOK * EDIM];
__device__ __half g_wh[NTOK * NTOK];
__device__ __half g_vT[EDIM * NTOK];
__device__ __half g_wv[NTOK * EDIM];
__device__ __half g_Wqkv[NLAYER * 3 * EDIM * EDIM];
__device__ __half g_Wo[NLAYER * EDIM * EDIM];

// ---------------------------------------------------------------------------
// Helpers
// ---------------------------------------------------------------------------
__device__ __forceinline__ uint32_t s2u(const void* p) {
    uint32_t a;
    asm("{ .reg .u64 t; cvta.to.shared.u64 t, %1; cvt.u32.u64 %0, t; }" : "=r"(a) : "l"(p));
    return a;
}
#define CPA(sm, gp) \
    asm volatile("cp.async.cg.shared.global [%0], [%1], 16;" :: "r"(sm), "l"(gp))
#define CPA_COMMIT() asm volatile("cp.async.commit_group;")
#define CPA_WAIT2()  asm volatile("cp.async.wait_group 2;")

#define LDSM4(r0, r1, r2, r3, addr)                                          \
    asm volatile("ldmatrix.sync.aligned.m8n8.x4.shared.b16 {%0,%1,%2,%3}, [%4];" \
                 : "=r"(r0), "=r"(r1), "=r"(r2), "=r"(r3) : "r"(addr))

__device__ __forceinline__ void mma16816(float* c, const uint32_t* a, const uint32_t* b) {
    asm volatile(
        "mma.sync.aligned.m16n8k16.row.col.f32.f16.f16.f32 "
        "{%0,%1,%2,%3}, {%4,%5,%6,%7}, {%8,%9}, {%0,%1,%2,%3};"
        : "+f"(c[0]), "+f"(c[1]), "+f"(c[2]), "+f"(c[3])
        : "r"(a[0]), "r"(a[1]), "r"(a[2]), "r"(a[3]), "r"(b[0]), "r"(b[1]));
}

__device__ __forceinline__ uint32_t pack2h(float a, float b) {
    __half2 t = __floats2half2_rn(a, b);
    return *reinterpret_cast<uint32_t*>(&t);
}

// SMEM: 4 stages; stage = 2 tiles (A, B) of 128 rows x 16 fp16, 48B pitch.
// (R8 mainloop configuration: best measured. DO NOT TOUCH.)
#define TILE_B   6144          // 128 * 48
#define STAGE_B  12288         // 2 tiles
#define SMEM_BYTES (4 * STAGE_B)   // 49152

// ---------------------------------------------------------------------------
// Split-K (xNSPLIT) tensor-core NT GEMM, single-pass fp16 (R8 mainloop):
//   partial[kz] = sum_{k in slice kz} A*B^T   (fp32 out)
//   CSKIP: skip blocks strictly above diagonal;  KLIM: Keff = (by+1)*128
// 4-stage cp.async pipeline, ONE __syncthreads per K=16 chunk.
// Prologue guarded (supports nch >= 2).
// ---------------------------------------------------------------------------
template<int NSPLIT, bool CSKIP, bool KLIM>
__global__ void __launch_bounds__(256, 2) gemm_mma(
    const __half* __restrict__ A, int lda,
    const __half* __restrict__ B, int ldb,
    float* __restrict__ Cf0, float* __restrict__ Cf1,
    float* __restrict__ Cf2, float* __restrict__ Cf3, int ldc,
    int K, float alpha)
{
    const int bx = blockIdx.x, by = blockIdx.y, kz = blockIdx.z;
    if (CSKIP && bx > by) return;
    const int Keff  = KLIM ? min(K, (by + 1) * 128) : K;
    const int slice = Keff / NSPLIT;       // multiple of 32
    const int k0    = kz * slice;
    const int nch   = slice / 16;          // >= 2 in all uses

    float* __restrict__ Cp = (kz == 0) ? Cf0 : (kz == 1) ? Cf1
                           : (kz == 2) ? Cf2 : Cf3;

    extern __shared__ __align__(128) char smem[];
    const uint32_t sb = s2u(smem);

    const int tid  = threadIdx.x;
    const int wid  = tid >> 5, lane = tid & 31;
    const int wm   = (wid & 1) * 64;
    const int wn   = (wid >> 1) * 32;

    const __half* Ab = A + (size_t)(by * 128) * lda;
    const __half* Bb = B + (size_t)(bx * 128) * ldb;

    const uint32_t a_row = lane & 15;
    const uint32_t a_k   = (lane >> 4) * 16;
    const uint32_t b_row = (lane & 7) + (lane >> 4) * 8;
    const uint32_t b_k   = ((lane >> 3) & 1) * 16;

    float acc[4][4][4];
#pragma unroll
    for (int i = 0; i < 4; i++)
#pragma unroll
        for (int j = 0; j < 4; j++)
#pragma unroll
            for (int r = 0; r < 4; r++) acc[i][j][r] = 0.f;

    const int lrow = tid >> 1;
    const int lc   = tid & 1;
    const uint32_t lso = (uint32_t)lrow * 48 + lc * 16;
    const size_t   lga = (size_t)lrow * lda + lc * 8;
    const size_t   lgb = (size_t)lrow * ldb + lc * 8;

    auto load_stage = [&](int stage, int kt) {
        uint32_t base = sb + (uint32_t)stage * STAGE_B + lso;
        CPA(base,          Ab + lga + kt);
        CPA(base + TILE_B, Bb + lgb + kt);
    };

    // guarded prologue: supports nch >= 2 (empty groups keep count uniform)
#pragma unroll
    for (int s = 0; s < 3; s++) {
        if (s < nch) load_stage(s, k0 + s * 16);
        CPA_COMMIT();
    }

    for (int c = 0; c < nch; c++) {
        CPA_WAIT2();
        __syncthreads();
        if (c + 3 < nch) load_stage((c + 3) & 3, k0 + (c + 3) * 16);
        CPA_COMMIT();

        const uint32_t base = sb + (uint32_t)(c & 3) * STAGE_B;

        uint32_t bf[8];
        {
            uint32_t bb = base + TILE_B + (wn + b_row) * 48 + b_k;
            LDSM4(bf[0], bf[1], bf[2], bf[3], bb);
            LDSM4(bf[4], bf[5], bf[6], bf[7], bb + 16 * 48);
        }
#pragma unroll
        for (int mf = 0; mf < 4; mf++) {
            uint32_t ah[4];
            uint32_t ab = base + (wm + mf * 16 + a_row) * 48 + a_k;
            LDSM4(ah[0], ah[1], ah[2], ah[3], ab);
#pragma unroll
            for (int nf = 0; nf < 4; nf++)
                mma16816(acc[mf][nf], ah, bf + nf * 2);
        }
    }

#pragma unroll
    for (int mf = 0; mf < 4; mf++) {
#pragma unroll
        for (int nf = 0; nf < 4; nf++) {
            const float* cc = acc[mf][nf];
            int row0 = by * 128 + wm + mf * 16 + (lane >> 2);
            int col  = bx * 128 + wn + nf * 8 + (lane & 3) * 2;
            float2 v0 = make_float2(alpha * cc[0], alpha * cc[1]);
            float2 v1 = make_float2(alpha * cc[2], alpha * cc[3]);
            *(float2*)(Cp + (size_t)row0 * ldc + col) = v0;
            *(float2*)(Cp + (size_t)(row0 + 8) * ldc + col) = v1;
        }
    }
}

// ---------------------------------------------------------------------------
// Fused qkv combine + v transpose (R11 kernel; grid.x=48 full, 32 = q,k only).
// ---------------------------------------------------------------------------
__global__ __launch_bounds__(256) void combine_qkv_transpose(
    const float* __restrict__ p0, const float* __restrict__ p1,
    const float* __restrict__ bias,
    __half* __restrict__ qkv, __half* __restrict__ vT)
{
    __shared__ __half sh[64][65];
    const int c0 = blockIdx.x * 64, r0 = blockIdx.y * 64;
    const int tid = threadIdx.x;
    const int col4 = tid & 15;
    const int rbase = tid >> 4;
    const bool vtile = (c0 >= 2 * EDIM);

    float b0 = bias[c0 + col4 * 4 + 0];
    float b1 = bias[c0 + col4 * 4 + 1];
    float b2 = bias[c0 + col4 * 4 + 2];
    float b3 = bias[c0 + col4 * 4 + 3];

#pragma unroll
    for (int rr = 0; rr < 4; rr++) {
        int r = rbase + rr * 16;
        size_t idx4 = ((size_t)(r0 + r) * (3 * EDIM) + c0 + col4 * 4) >> 2;
        float4 a = ((const float4*)p0)[idx4];
        float4 b = ((const float4*)p1)[idx4];
        float v0 = a.x + b.x + b0, v1 = a.y + b.y + b1;
        float v2 = a.z + b.z + b2, v3 = a.w + b.w + b3;
        uint2 ph;
        ph.x = pack2h(v0, v1); ph.y = pack2h(v2, v3);
        ((uint2*)qkv)[idx4] = ph;
        if (vtile) {
            __half2 h01 = __floats2half2_rn(v0, v1);
            __half2 h23 = __floats2half2_rn(v2, v3);
            sh[r][col4 * 4 + 0] = __low2half(h01);
            sh[r][col4 * 4 + 1] = __high2half(h01);
            sh[r][col4 * 4 + 2] = __low2half(h23);
            sh[r][col4 * 4 + 3] = __high2half(h23);
        }
    }

    if (vtile) {
        __syncthreads();
        const int cc = tid & 63;
        const int rg = tid >> 6;
        __half tmp[16];
#pragma unroll
        for (int j = 0; j < 16; j++) tmp[j] = sh[rg * 16 + j][cc];
        size_t dst = (size_t)(c0 - 2 * EDIM + cc) * NTOK + r0 + rg * 16;
        *(uint4*)(vT + dst)     = *(uint4*)&tmp[0];
        *(uint4*)(vT + dst + 8) = *(uint4*)&tmp[8];
    }
}

// ---------------------------------------------------------------------------
// combine 4 split-K partials: v = (p0+p1)+(p2+p3) (+ bias); write fp16
// ---------------------------------------------------------------------------
__global__ void combine_split4(const float* __restrict__ p0, const float* __restrict__ p1,
                               const float* __restrict__ p2, const float* __restrict__ p3,
                               const float* __restrict__ bias,
                               __half* __restrict__ dst, int ncols, int n4)
{
    int idx = blockIdx.x * blockDim.x + threadIdx.x;
    if (idx >= n4) return;
    float4 a = ((const float4*)p0)[idx];
    float4 b = ((const float4*)p1)[idx];
    float4 c = ((const float4*)p2)[idx];
    float4 d = ((const float4*)p3)[idx];
    float v0 = (a.x + b.x) + (c.x + d.x);
    float v1 = (a.y + b.y) + (c.y + d.y);
    float v2 = (a.z + b.z) + (c.z + d.z);
    float v3 = (a.w + b.w) + (c.w + d.w);
    if (bias) {
        int col = (idx * 4) % ncols;
        v0 += bias[col]; v1 += bias[col + 1]; v2 += bias[col + 2]; v3 += bias[col + 3];
    }
    uint2 ph;
    ph.x = pack2h(v0, v1); ph.y = pack2h(v2, v3);
    ((uint2*)dst)[idx] = ph;
}

// combine 2 split-K partials (out-proj path)
__global__ void combine_split(const float* __restrict__ p0, const float* __restrict__ p1,
                              const float* __restrict__ bias,
                              __half* __restrict__ dst, int ncols, int n4)
{
    int idx = blockIdx.x * blockDim.x + threadIdx.x;
    if (idx >= n4) return;
    float4 a = ((const float4*)p0)[idx];
    float4 b = ((const float4*)p1)[idx];
    float v0 = a.x + b.x, v1 = a.y + b.y, v2 = a.z + b.z, v3 = a.w + b.w;
    if (bias) {
        int col = (idx * 4) % ncols;
        v0 += bias[col]; v1 += bias[col + 1]; v2 += bias[col + 2]; v3 += bias[col + 3];
    }
    uint2 ph;
    ph.x = pack2h(v0, v1); ph.y = pack2h(v2, v3);
    ((uint2*)dst)[idx] = ph;
}

// ---------------------------------------------------------------------------
// Causal softmax over row i (len = i+1); scores = p0 + p1 (2 partials).
// Vectorized (float4 / uint2) loads & stores; per-element arithmetic and
// reduction order identical to R15 (max is order-exact; exp/sum pass keeps
// the same thread->element mapping), so results are bit-identical.
//   wh fp16 written only when write_wh; out: first layer full row,
//   later layers j < len only (upper triangle addends are exactly 0).
// ---------------------------------------------------------------------------
__global__ __launch_bounds__(256) void softmax_causal_acc(
    const float* __restrict__ w0, const float* __restrict__ w1,
    __half* __restrict__ wh, float* __restrict__ out, int first, int write_wh)
{
    const int i = blockIdx.x;
    const int len = i + 1;
    const int limit = ((i >> 7) + 1) << 7;   // block-aligned, multiple of 128
    const int tid = threadIdx.x;

    __shared__ float row[NTOK];
    __shared__ float red[256];

    const float* wr0 = w0 + (size_t)i * NTOK;
    const float* wr1 = w1 + (size_t)i * NTOK;
    const float4* wr04 = (const float4*)wr0;
    const float4* wr14 = (const float4*)wr1;
    float4* row4 = (float4*)row;

    // Pass 1: row = p0 + p1, running max (vectorized; max is order-exact)
    float m = -3.4e38f;
    const int len4 = len >> 2;
    for (int j4 = tid; j4 < len4; j4 += 256) {
        float4 a = wr04[j4], b = wr14[j4];
        float4 v = make_float4(a.x + b.x, a.y + b.y, a.z + b.z, a.w + b.w);
        row4[j4] = v;
        m = fmaxf(m, fmaxf(fmaxf(v.x, v.y), fmaxf(v.z, v.w)));
    }
    for (int j = len4 * 4 + tid; j < len; j += 256) {   // tail (<4 elems)
        float v = wr0[j] + wr1[j];
        row[j] = v;
        m = fmaxf(m, v);
    }
    red[tid] = m;
    __syncthreads();
#pragma unroll
    for (int s = 128; s > 0; s >>= 1) {
        if (tid < s) red[tid] = fmaxf(red[tid], red[tid + s]);
        __syncthreads();
    }
    m = red[0];
    __syncthreads();

    // Pass 2: exp + sum — EXACT same order as R15 (bit-identical sum)
    float sum = 0.f;
    for (int j = tid; j < len; j += 256) {
        float e = __expf(row[j] - m);
        row[j] = e;
        sum += e;
    }
    red[tid] = sum;
    __syncthreads();
#pragma unroll
    for (int s = 128; s > 0; s >>= 1) {
        if (tid < s) red[tid] += red[tid + s];
        __syncthreads();
    }
    const float inv = 1.0f / red[0];

    float* outr = out + (size_t)i * NTOK;
    if (write_wh) {
        // limit is a multiple of 128 -> uint2 (4 halves) stores are exact
        uint2* hr4 = (uint2*)(wh + (size_t)i * NTOK);
        const int lim4 = limit >> 2;
        for (int j4 = tid; j4 < lim4; j4 += 256) {
            int j = j4 * 4;
            float v0 = (j + 0 < len) ? row[j + 0] * inv : 0.f;
            float v1 = (j + 1 < len) ? row[j + 1] * inv : 0.f;
            float v2 = (j + 2 < len) ? row[j + 2] * inv : 0.f;
            float v3 = (j + 3 < len) ? row[j + 3] * inv : 0.f;
            uint2 ph;
            ph.x = pack2h(v0, v1); ph.y = pack2h(v2, v3);
            hr4[j4] = ph;
        }
    }
    if (first) {
        float4* o4 = (float4*)outr;
        for (int j4 = tid; j4 < NTOK / 4; j4 += 256) {
            int j = j4 * 4;
            float4 v;
            v.x = (j + 0 < len) ? 0.25f * (row[j + 0] * inv) : 0.f;
            v.y = (j + 1 < len) ? 0.25f * (row[j + 1] * inv) : 0.f;
            v.z = (j + 2 < len) ? 0.25f * (row[j + 2] * inv) : 0.f;
            v.w = (j + 3 < len) ? 0.25f * (row[j + 3] * inv) : 0.f;
            o4[j4] = v;
        }
    } else {
        float4* o4 = (float4*)outr;
        const int l4 = len >> 2;
        for (int j4 = tid; j4 < l4; j4 += 256) {
            int j = j4 * 4;
            float4 o = o4[j4];
            o.x += 0.25f * (row[j + 0] * inv);
            o.y += 0.25f * (row[j + 1] * inv);
            o.z += 0.25f * (row[j + 2] * inv);
            o.w += 0.25f * (row[j + 3] * inv);
            o4[j4] = o;
        }
        for (int j = l4 * 4 + tid; j < len; j += 256)
            outr[j] += 0.25f * (row[j] * inv);
    }
}

// fp32 -> fp16 convert (vectorized by 4)
__global__ void conv_f16(const float* __restrict__ src,
                         __half* __restrict__ dst, int n4)
{
    int idx = blockIdx.x * blockDim.x + threadIdx.x;
    if (idx >= n4) return;
    float4 v = ((const float4*)src)[idx];
    uint2 ph;
    ph.x = pack2h(v.x, v.y); ph.y = pack2h(v.z, v.w);
    ((uint2*)dst)[idx] = ph;
}

// ---------------------------------------------------------------------------
extern "C" void kernel_launch(void* const* d_in, const int* in_sizes, int n_in,
                              void* d_out, int out_size)
{
    const float* mentions = (const float*)d_in[0];  // [2048,1024]
    const float* Wqkv     = (const float*)d_in[1];  // [4,3072,1024]
    const float* bqkv     = (const float*)d_in[2];  // [4,3072]
    const float* Wo       = (const float*)d_in[3];  // [4,1024,1024]
    const float* bo       = (const float*)d_in[4];  // [4,1024]
    float* out            = (float*)d_out;          // [2048,2048]

    __half *x, *qkv, *wh, *vT, *wv, *Wq, *Wl;
    float *p0, *p1, *sp0, *sp1, *sp2, *sp3;
    cudaGetSymbolAddress((void**)&x, g_x);
    cudaGetSymbolAddress((void**)&qkv, g_qkv);
    cudaGetSymbolAddress((void**)&p0, g_p0);   cudaGetSymbolAddress((void**)&p1, g_p1);
    cudaGetSymbolAddress((void**)&sp0, g_sp0); cudaGetSymbolAddress((void**)&sp1, g_sp1);
    cudaGetSymbolAddress((void**)&sp2, g_sp2); cudaGetSymbolAddress((void**)&sp3, g_sp3);
    cudaGetSymbolAddress((void**)&wh, g_wh);
    cudaGetSymbolAddress((void**)&vT, g_vT);
    cudaGetSymbolAddress((void**)&wv, g_wv);
    cudaGetSymbolAddress((void**)&Wq, g_Wqkv);
    cudaGetSymbolAddress((void**)&Wl, g_Wo);

    cudaFuncSetAttribute(gemm_mma<2, false, false>,
                         cudaFuncAttributeMaxDynamicSharedMemorySize, SMEM_BYTES);
    cudaFuncSetAttribute(gemm_mma<2, true, false>,
                         cudaFuncAttributeMaxDynamicSharedMemorySize, SMEM_BYTES);
    cudaFuncSetAttribute(gemm_mma<4, false, true>,
                         cudaFuncAttributeMaxDynamicSharedMemorySize, SMEM_BYTES);

    const float scale = 1.0f / 32.0f;   // 1/sqrt(1024)

    // Convert weights + input to fp16. Dead weights skipped: layer-3 Wo
    // entirely; layer-3 Wqkv v-rows (rows 2048..3071 of layer 3).
    {
        int n4 = (3 * 3 * EDIM + 2 * EDIM) * EDIM / 4;   // 3 full layers + q,k of layer 3
        conv_f16<<<(n4 + 255) / 256, 256>>>(Wqkv, Wq, n4);
        n4 = (NLAYER - 1) * EDIM * EDIM / 4;
        conv_f16<<<(n4 + 255) / 256, 256>>>(Wo, Wl, n4);
        n4 = NTOK * EDIM / 4;
        conv_f16<<<(n4 + 255) / 256, 256>>>(mentions, x, n4);
    }

    for (int l = 0; l < NLAYER; l++) {
        const bool last = (l == NLAYER - 1);
        const __half* Wqh = Wq + (size_t)l * 3 * EDIM * EDIM;
        const __half* Woh = Wl + (size_t)l * EDIM * EDIM;
        const float* bq = bqkv + (size_t)l * 3 * EDIM;
        const float* bl = bo   + (size_t)l * EDIM;

        // qkv partials = x @ Wqkv^T (split-K x2). Last layer: q,k cols only.
        gemm_mma<2, false, false><<<dim3(last ? 16 : 24, 16, 2), 256, SMEM_BYTES>>>(
            x, EDIM, Wqh, EDIM, p0, p1, p0, p1, 3 * EDIM, EDIM, 1.0f);
        // qkv = p0 + p1 + bqkv -> fp16 (+ vT on non-last layers)
        combine_qkv_transpose<<<dim3(last ? 32 : 48, 32), 256>>>(p0, p1, bq, qkv, vT);

        // scores partials = scale * q @ k^T  (split-K x2, lower blocks only)
        gemm_mma<2, true, false><<<dim3(16, 16, 2), 256, SMEM_BYTES>>>(
            qkv, 3 * EDIM, qkv + EDIM, 3 * EDIM, p0, p1, p0, p1, NTOK,
            EDIM, scale);

        // softmax -> out accumulation (+ wh fp16 on non-last layers)
        softmax_causal_acc<<<NTOK, 256>>>(p0, p1, wh, out,
                                          l == 0 ? 1 : 0, last ? 0 : 1);

        if (last) break;   // wv / out-proj / x are dead beyond this point

        // wv partials = w @ v  (split-K x4: balances the KLIM single wave)
        gemm_mma<4, false, true><<<dim3(8, 16, 4), 256, SMEM_BYTES>>>(
            wh, NTOK, vT, NTOK, sp0, sp1, sp2, sp3, EDIM, NTOK, 1.0f);
        combine_split4<<<(NTOK * EDIM / 4 + 255) / 256, 256>>>(
            sp0, sp1, sp2, sp3, nullptr, wv, EDIM, NTOK * EDIM / 4);

        // x partials = wv @ Wo^T  (split-K x2, balanced single wave)
        gemm_mma<2, false, false><<<dim3(8, 16, 2), 256, SMEM_BYTES>>>(
            wv, EDIM, Woh, EDIM, sp0, sp1, sp0, sp1, EDIM, EDIM, 1.0f);
        combine_split<<<(NTOK * EDIM / 4 + 255) / 256, 256>>>(
            sp0, sp1, bl, x, EDIM, NTOK * EDIM / 4);
    }
}

// round 17
// speedup vs baseline: 1.2097x; 1.0033x over previous
#include <cuda_runtime.h>
#include <cuda_fp16.h>
#include <stdint.h>
#include <math.h>

#define NTOK 2048
#define EDIM 1024
#define NLAYER 4

// ---------------------------------------------------------------------------
// Scratch (device globals — allocation is forbidden). Pure fp16 operands.
// ---------------------------------------------------------------------------
__device__ __half g_x[NTOK * EDIM];
__device__ __half g_qkv[NTOK * 3 * EDIM];
__device__ float  g_p0[NTOK * 3 * EDIM];   // qkv / scores partials (x2)
__device__ float  g_p1[NTOK * 3 * EDIM];
__device__ float  g_sp0[NTOK * EDIM];      // wv(x4) / out-proj(x2) partials
__device__ float  g_sp1[NTOK * EDIM];
__device__ float  g_sp2[NTOK * EDIM];
__device__ float  g_sp3[NTOK * EDIM];
__device__ __half g_wh[NTOK * NTOK];
__device__ __half g_vT[EDIM * NTOK];
__device__ __half g_wv[NTOK * EDIM];
__device__ __half g_Wqkv[NLAYER * 3 * EDIM * EDIM];
__device__ __half g_Wo[NLAYER * EDIM * EDIM];

// ---------------------------------------------------------------------------
// Helpers
// ---------------------------------------------------------------------------
__device__ __forceinline__ uint32_t s2u(const void* p) {
    uint32_t a;
    asm("{ .reg .u64 t; cvta.to.shared.u64 t, %1; cvt.u32.u64 %0, t; }" : "=r"(a) : "l"(p));
    return a;
}
#define CPA(sm, gp) \
    asm volatile("cp.async.cg.shared.global [%0], [%1], 16;" :: "r"(sm), "l"(gp))
#define CPA_COMMIT() asm volatile("cp.async.commit_group;")
#define CPA_WAIT2()  asm volatile("cp.async.wait_group 2;")

#define LDSM4(r0, r1, r2, r3, addr)                                          \
    asm volatile("ldmatrix.sync.aligned.m8n8.x4.shared.b16 {%0,%1,%2,%3}, [%4];" \
                 : "=r"(r0), "=r"(r1), "=r"(r2), "=r"(r3) : "r"(addr))

__device__ __forceinline__ void mma16816(float* c, const uint32_t* a, const uint32_t* b) {
    asm volatile(
        "mma.sync.aligned.m16n8k16.row.col.f32.f16.f16.f32 "
        "{%0,%1,%2,%3}, {%4,%5,%6,%7}, {%8,%9}, {%0,%1,%2,%3};"
        : "+f"(c[0]), "+f"(c[1]), "+f"(c[2]), "+f"(c[3])
        : "r"(a[0]), "r"(a[1]), "r"(a[2]), "r"(a[3]), "r"(b[0]), "r"(b[1]));
}

__device__ __forceinline__ uint32_t pack2h(float a, float b) {
    __half2 t = __floats2half2_rn(a, b);
    return *reinterpret_cast<uint32_t*>(&t);
}

// SMEM: 4 stages; stage = 2 tiles (A, B) of 128 rows x 16 fp16, 48B pitch.
// (R8 mainloop configuration: best measured. DO NOT TOUCH.)
#define TILE_B   6144          // 128 * 48
#define STAGE_B  12288         // 2 tiles
#define SMEM_BYTES (4 * STAGE_B)   // 49152

// ---------------------------------------------------------------------------
// Split-K (xNSPLIT) tensor-core NT GEMM, single-pass fp16 (R8 mainloop):
//   partial[kz] = sum_{k in slice kz} A*B^T   (fp32 out)
//   TRIPACK: grid.x linearizes the 136 lower-tri blocks (every CTA live)
//   KLIM:    Keff = (by+1)*128
// 4-stage cp.async pipeline, ONE __syncthreads per K=16 chunk.
// Prologue guarded (supports nch >= 2).
// ---------------------------------------------------------------------------
template<int NSPLIT, bool TRIPACK, bool KLIM>
__global__ void __launch_bounds__(256, 2) gemm_mma(
    const __half* __restrict__ A, int lda,
    const __half* __restrict__ B, int ldb,
    float* __restrict__ Cf0, float* __restrict__ Cf1,
    float* __restrict__ Cf2, float* __restrict__ Cf3, int ldc,
    int K, float alpha)
{
    int bx, by;
    if (TRIPACK) {
        // decode linear lower-tri index t -> (by, bx), bx <= by
        const int t = blockIdx.x;
        int r = (int)((sqrtf(8.0f * (float)t + 1.0f) - 1.0f) * 0.5f);
        // exact fixup (float sqrt can be off by one)
        while ((r + 1) * (r + 2) / 2 <= t) r++;
        while (r * (r + 1) / 2 > t) r--;
        by = r;
        bx = t - r * (r + 1) / 2;
    } else {
        bx = blockIdx.x; by = blockIdx.y;
    }
    const int kz = blockIdx.z;
    const int Keff  = KLIM ? min(K, (by + 1) * 128) : K;
    const int slice = Keff / NSPLIT;       // multiple of 32
    const int k0    = kz * slice;
    const int nch   = slice / 16;          // >= 2 in all uses

    float* __restrict__ Cp = (kz == 0) ? Cf0 : (kz == 1) ? Cf1
                           : (kz == 2) ? Cf2 : Cf3;

    extern __shared__ __align__(128) char smem[];
    const uint32_t sb = s2u(smem);

    const int tid  = threadIdx.x;
    const int wid  = tid >> 5, lane = tid & 31;
    const int wm   = (wid & 1) * 64;
    const int wn   = (wid >> 1) * 32;

    const __half* Ab = A + (size_t)(by * 128) * lda;
    const __half* Bb = B + (size_t)(bx * 128) * ldb;

    const uint32_t a_row = lane & 15;
    const uint32_t a_k   = (lane >> 4) * 16;
    const uint32_t b_row = (lane & 7) + (lane >> 4) * 8;
    const uint32_t b_k   = ((lane >> 3) & 1) * 16;

    float acc[4][4][4];
#pragma unroll
    for (int i = 0; i < 4; i++)
#pragma unroll
        for (int j = 0; j < 4; j++)
#pragma unroll
            for (int r = 0; r < 4; r++) acc[i][j][r] = 0.f;

    const int lrow = tid >> 1;
    const int lc   = tid & 1;
    const uint32_t lso = (uint32_t)lrow * 48 + lc * 16;
    const size_t   lga = (size_t)lrow * lda + lc * 8;
    const size_t   lgb = (size_t)lrow * ldb + lc * 8;

    auto load_stage = [&](int stage, int kt) {
        uint32_t base = sb + (uint32_t)stage * STAGE_B + lso;
        CPA(base,          Ab + lga + kt);
        CPA(base + TILE_B, Bb + lgb + kt);
    };

    // guarded prologue: supports nch >= 2 (empty groups keep count uniform)
#pragma unroll
    for (int s = 0; s < 3; s++) {
        if (s < nch) load_stage(s, k0 + s * 16);
        CPA_COMMIT();
    }

    for (int c = 0; c < nch; c++) {
        CPA_WAIT2();
        __syncthreads();
        if (c + 3 < nch) load_stage((c + 3) & 3, k0 + (c + 3) * 16);
        CPA_COMMIT();

        const uint32_t base = sb + (uint32_t)(c & 3) * STAGE_B;

        uint32_t bf[8];
        {
            uint32_t bb = base + TILE_B + (wn + b_row) * 48 + b_k;
            LDSM4(bf[0], bf[1], bf[2], bf[3], bb);
            LDSM4(bf[4], bf[5], bf[6], bf[7], bb + 16 * 48);
        }
#pragma unroll
        for (int mf = 0; mf < 4; mf++) {
            uint32_t ah[4];
            uint32_t ab = base + (wm + mf * 16 + a_row) * 48 + a_k;
            LDSM4(ah[0], ah[1], ah[2], ah[3], ab);
#pragma unroll
            for (int nf = 0; nf < 4; nf++)
                mma16816(acc[mf][nf], ah, bf + nf * 2);
        }
    }

#pragma unroll
    for (int mf = 0; mf < 4; mf++) {
#pragma unroll
        for (int nf = 0; nf < 4; nf++) {
            const float* cc = acc[mf][nf];
            int row0 = by * 128 + wm + mf * 16 + (lane >> 2);
            int col  = bx * 128 + wn + nf * 8 + (lane & 3) * 2;
            float2 v0 = make_float2(alpha * cc[0], alpha * cc[1]);
            float2 v1 = make_float2(alpha * cc[2], alpha * cc[3]);
            *(float2*)(Cp + (size_t)row0 * ldc + col) = v0;
            *(float2*)(Cp + (size_t)(row0 + 8) * ldc + col) = v1;
        }
    }
}

// ---------------------------------------------------------------------------
// Fused qkv combine + v transpose (R11 kernel; grid.x=48 full, 32 = q,k only).
// ---------------------------------------------------------------------------
__global__ __launch_bounds__(256) void combine_qkv_transpose(
    const float* __restrict__ p0, const float* __restrict__ p1,
    const float* __restrict__ bias,
    __half* __restrict__ qkv, __half* __restrict__ vT)
{
    __shared__ __half sh[64][65];
    const int c0 = blockIdx.x * 64, r0 = blockIdx.y * 64;
    const int tid = threadIdx.x;
    const int col4 = tid & 15;
    const int rbase = tid >> 4;
    const bool vtile = (c0 >= 2 * EDIM);

    float b0 = bias[c0 + col4 * 4 + 0];
    float b1 = bias[c0 + col4 * 4 + 1];
    float b2 = bias[c0 + col4 * 4 + 2];
    float b3 = bias[c0 + col4 * 4 + 3];

#pragma unroll
    for (int rr = 0; rr < 4; rr++) {
        int r = rbase + rr * 16;
        size_t idx4 = ((size_t)(r0 + r) * (3 * EDIM) + c0 + col4 * 4) >> 2;
        float4 a = ((const float4*)p0)[idx4];
        float4 b = ((const float4*)p1)[idx4];
        float v0 = a.x + b.x + b0, v1 = a.y + b.y + b1;
        float v2 = a.z + b.z + b2, v3 = a.w + b.w + b3;
        uint2 ph;
        ph.x = pack2h(v0, v1); ph.y = pack2h(v2, v3);
        ((uint2*)qkv)[idx4] = ph;
        if (vtile) {
            __half2 h01 = __floats2half2_rn(v0, v1);
            __half2 h23 = __floats2half2_rn(v2, v3);
            sh[r][col4 * 4 + 0] = __low2half(h01);
            sh[r][col4 * 4 + 1] = __high2half(h01);
            sh[r][col4 * 4 + 2] = __low2half(h23);
            sh[r][col4 * 4 + 3] = __high2half(h23);
        }
    }

    if (vtile) {
        __syncthreads();
        const int cc = tid & 63;
        const int rg = tid >> 6;
        __half tmp[16];
#pragma unroll
        for (int j = 0; j < 16; j++) tmp[j] = sh[rg * 16 + j][cc];
        size_t dst = (size_t)(c0 - 2 * EDIM + cc) * NTOK + r0 + rg * 16;
        *(uint4*)(vT + dst)     = *(uint4*)&tmp[0];
        *(uint4*)(vT + dst + 8) = *(uint4*)&tmp[8];
    }
}

// ---------------------------------------------------------------------------
// combine 4 split-K partials: v = (p0+p1)+(p2+p3) (+ bias); write fp16
// 512-thread blocks (pure element-wise; mapping unchanged -> bit-exact).
// ---------------------------------------------------------------------------
__global__ __launch_bounds__(512) void combine_split4(
    const float* __restrict__ p0, const float* __restrict__ p1,
    const float* __restrict__ p2, const float* __restrict__ p3,
    const float* __restrict__ bias,
    __half* __restrict__ dst, int ncols, int n4)
{
    int idx = blockIdx.x * blockDim.x + threadIdx.x;
    if (idx >= n4) return;
    float4 a = ((const float4*)p0)[idx];
    float4 b = ((const float4*)p1)[idx];
    float4 c = ((const float4*)p2)[idx];
    float4 d = ((const float4*)p3)[idx];
    float v0 = (a.x + b.x) + (c.x + d.x);
    float v1 = (a.y + b.y) + (c.y + d.y);
    float v2 = (a.z + b.z) + (c.z + d.z);
    float v3 = (a.w + b.w) + (c.w + d.w);
    if (bias) {
        int col = (idx * 4) % ncols;
        v0 += bias[col]; v1 += bias[col + 1]; v2 += bias[col + 2]; v3 += bias[col + 3];
    }
    uint2 ph;
    ph.x = pack2h(v0, v1); ph.y = pack2h(v2, v3);
    ((uint2*)dst)[idx] = ph;
}

// combine 2 split-K partials (out-proj path)
__global__ void combine_split(const float* __restrict__ p0, const float* __restrict__ p1,
                              const float* __restrict__ bias,
                              __half* __restrict__ dst, int ncols, int n4)
{
    int idx = blockIdx.x * blockDim.x + threadIdx.x;
    if (idx >= n4) return;
    float4 a = ((const float4*)p0)[idx];
    float4 b = ((const float4*)p1)[idx];
    float v0 = a.x + b.x, v1 = a.y + b.y, v2 = a.z + b.z, v3 = a.w + b.w;
    if (bias) {
        int col = (idx * 4) % ncols;
        v0 += bias[col]; v1 += bias[col + 1]; v2 += bias[col + 2]; v3 += bias[col + 3];
    }
    uint2 ph;
    ph.x = pack2h(v0, v1); ph.y = pack2h(v2, v3);
    ((uint2*)dst)[idx] = ph;
}

// ---------------------------------------------------------------------------
// Causal softmax over row i (len = i+1); scores = p0 + p1 (2 partials).
// Vectorized; per-element arithmetic and reduction order identical to R16.
// ---------------------------------------------------------------------------
__global__ __launch_bounds__(256) void softmax_causal_acc(
    const float* __restrict__ w0, const float* __restrict__ w1,
    __half* __restrict__ wh, float* __restrict__ out, int first, int write_wh)
{
    const int i = blockIdx.x;
    const int len = i + 1;
    const int limit = ((i >> 7) + 1) << 7;   // block-aligned, multiple of 128
    const int tid = threadIdx.x;

    __shared__ float row[NTOK];
    __shared__ float red[256];

    const float* wr0 = w0 + (size_t)i * NTOK;
    const float* wr1 = w1 + (size_t)i * NTOK;
    const float4* wr04 = (const float4*)wr0;
    const float4* wr14 = (const float4*)wr1;
    float4* row4 = (float4*)row;

    float m = -3.4e38f;
    const int len4 = len >> 2;
    for (int j4 = tid; j4 < len4; j4 += 256) {
        float4 a = wr04[j4], b = wr14[j4];
        float4 v = make_float4(a.x + b.x, a.y + b.y, a.z + b.z, a.w + b.w);
        row4[j4] = v;
        m = fmaxf(m, fmaxf(fmaxf(v.x, v.y), fmaxf(v.z, v.w)));
    }
    for (int j = len4 * 4 + tid; j < len; j += 256) {
        float v = wr0[j] + wr1[j];
        row[j] = v;
        m = fmaxf(m, v);
    }
    red[tid] = m;
    __syncthreads();
#pragma unroll
    for (int s = 128; s > 0; s >>= 1) {
        if (tid < s) red[tid] = fmaxf(red[tid], red[tid + s]);
        __syncthreads();
    }
    m = red[0];
    __syncthreads();

    float sum = 0.f;
    for (int j = tid; j < len; j += 256) {
        float e = __expf(row[j] - m);
        row[j] = e;
        sum += e;
    }
    red[tid] = sum;
    __syncthreads();
#pragma unroll
    for (int s = 128; s > 0; s >>= 1) {
        if (tid < s) red[tid] += red[tid + s];
        __syncthreads();
    }
    const float inv = 1.0f / red[0];

    float* outr = out + (size_t)i * NTOK;
    if (write_wh) {
        uint2* hr4 = (uint2*)(wh + (size_t)i * NTOK);
        const int lim4 = limit >> 2;
        for (int j4 = tid; j4 < lim4; j4 += 256) {
            int j = j4 * 4;
            float v0 = (j + 0 < len) ? row[j + 0] * inv : 0.f;
            float v1 = (j + 1 < len) ? row[j + 1] * inv : 0.f;
            float v2 = (j + 2 < len) ? row[j + 2] * inv : 0.f;
            float v3 = (j + 3 < len) ? row[j + 3] * inv : 0.f;
            uint2 ph;
            ph.x = pack2h(v0, v1); ph.y = pack2h(v2, v3);
            hr4[j4] = ph;
        }
    }
    if (first) {
        float4* o4 = (float4*)outr;
        for (int j4 = tid; j4 < NTOK / 4; j4 += 256) {
            int j = j4 * 4;
            float4 v;
            v.x = (j + 0 < len) ? 0.25f * (row[j + 0] * inv) : 0.f;
            v.y = (j + 1 < len) ? 0.25f * (row[j + 1] * inv) : 0.f;
            v.z = (j + 2 < len) ? 0.25f * (row[j + 2] * inv) : 0.f;
            v.w = (j + 3 < len) ? 0.25f * (row[j + 3] * inv) : 0.f;
            o4[j4] = v;
        }
    } else {
        float4* o4 = (float4*)outr;
        const int l4 = len >> 2;
        for (int j4 = tid; j4 < l4; j4 += 256) {
            int j = j4 * 4;
            float4 o = o4[j4];
            o.x += 0.25f * (row[j + 0] * inv);
            o.y += 0.25f * (row[j + 1] * inv);
            o.z += 0.25f * (row[j + 2] * inv);
            o.w += 0.25f * (row[j + 3] * inv);
            o4[j4] = o;
        }
        for (int j = l4 * 4 + tid; j < len; j += 256)
            outr[j] += 0.25f * (row[j] * inv);
    }
}

// ---------------------------------------------------------------------------
// Fused fp32 -> fp16 conversion of all live inputs in ONE launch.
//   region 0: Wqkv live rows (3 layers full + layer-3 q,k) -> Wq
//   region 1: Wo layers 0..2 -> Wl
//   region 2: mentions -> x
// ---------------------------------------------------------------------------
#define CONV_N4_WQ  ((3 * 3 * EDIM + 2 * EDIM) * EDIM / 4)
#define CONV_N4_WO  ((NLAYER - 1) * EDIM * EDIM / 4)
#define CONV_N4_X   (NTOK * EDIM / 4)
__global__ __launch_bounds__(256) void conv_all_f16(
    const float* __restrict__ Wqkv, __half* __restrict__ Wq,
    const float* __restrict__ Wo,   __half* __restrict__ Wl,
    const float* __restrict__ mentions, __half* __restrict__ x)
{
    int idx = blockIdx.x * blockDim.x + threadIdx.x;
    const float* src; __half* dst;
    if (idx < CONV_N4_WQ) {
        src = Wqkv; dst = Wq;
    } else if (idx < CONV_N4_WQ + CONV_N4_WO) {
        idx -= CONV_N4_WQ; src = Wo; dst = Wl;
    } else if (idx < CONV_N4_WQ + CONV_N4_WO + CONV_N4_X) {
        idx -= CONV_N4_WQ + CONV_N4_WO; src = mentions; dst = x;
    } else return;
    float4 v = ((const float4*)src)[idx];
    uint2 ph;
    ph.x = pack2h(v.x, v.y); ph.y = pack2h(v.z, v.w);
    ((uint2*)dst)[idx] = ph;
}

// ---------------------------------------------------------------------------
extern "C" void kernel_launch(void* const* d_in, const int* in_sizes, int n_in,
                              void* d_out, int out_size)
{
    const float* mentions = (const float*)d_in[0];  // [2048,1024]
    const float* Wqkv     = (const float*)d_in[1];  // [4,3072,1024]
    const float* bqkv     = (const float*)d_in[2];  // [4,3072]
    const float* Wo       = (const float*)d_in[3];  // [4,1024,1024]
    const float* bo       = (const float*)d_in[4];  // [4,1024]
    float* out            = (float*)d_out;          // [2048,2048]

    __half *x, *qkv, *wh, *vT, *wv, *Wq, *Wl;
    float *p0, *p1, *sp0, *sp1, *sp2, *sp3;
    cudaGetSymbolAddress((void**)&x, g_x);
    cudaGetSymbolAddress((void**)&qkv, g_qkv);
    cudaGetSymbolAddress((void**)&p0, g_p0);   cudaGetSymbolAddress((void**)&p1, g_p1);
    cudaGetSymbolAddress((void**)&sp0, g_sp0); cudaGetSymbolAddress((void**)&sp1, g_sp1);
    cudaGetSymbolAddress((void**)&sp2, g_sp2); cudaGetSymbolAddress((void**)&sp3, g_sp3);
    cudaGetSymbolAddress((void**)&wh, g_wh);
    cudaGetSymbolAddress((void**)&vT, g_vT);
    cudaGetSymbolAddress((void**)&wv, g_wv);
    cudaGetSymbolAddress((void**)&Wq, g_Wqkv);
    cudaGetSymbolAddress((void**)&Wl, g_Wo);

    cudaFuncSetAttribute(gemm_mma<2, false, false>,
                         cudaFuncAttributeMaxDynamicSharedMemorySize, SMEM_BYTES);
    cudaFuncSetAttribute(gemm_mma<2, true, false>,
                         cudaFuncAttributeMaxDynamicSharedMemorySize, SMEM_BYTES);
    cudaFuncSetAttribute(gemm_mma<4, false, true>,
                         cudaFuncAttributeMaxDynamicSharedMemorySize, SMEM_BYTES);

    const float scale = 1.0f / 32.0f;   // 1/sqrt(1024)

    // Convert all live fp32 inputs -> fp16 in one launch
    {
        int n4 = CONV_N4_WQ + CONV_N4_WO + CONV_N4_X;
        conv_all_f16<<<(n4 + 255) / 256, 256>>>(Wqkv, Wq, Wo, Wl, mentions, x);
    }

    for (int l = 0; l < NLAYER; l++) {
        const bool last = (l == NLAYER - 1);
        const __half* Wqh = Wq + (size_t)l * 3 * EDIM * EDIM;
        const __half* Woh = Wl + (size_t)l * EDIM * EDIM;
        const float* bq = bqkv + (size_t)l * 3 * EDIM;
        const float* bl = bo   + (size_t)l * EDIM;

        // qkv partials = x @ Wqkv^T (split-K x2). Last layer: q,k cols only.
        gemm_mma<2, false, false><<<dim3(last ? 16 : 24, 16, 2), 256, SMEM_BYTES>>>(
            x, EDIM, Wqh, EDIM, p0, p1, p0, p1, 3 * EDIM, EDIM, 1.0f);
        // qkv = p0 + p1 + bqkv -> fp16 (+ vT on non-last layers)
        combine_qkv_transpose<<<dim3(last ? 32 : 48, 32), 256>>>(p0, p1, bq, qkv, vT);

        // scores partials = scale * q @ k^T  (split-K x2, PACKED lower-tri grid)
        gemm_mma<2, true, false><<<dim3(136, 1, 2), 256, SMEM_BYTES>>>(
            qkv, 3 * EDIM, qkv + EDIM, 3 * EDIM, p0, p1, p0, p1, NTOK,
            EDIM, scale);

        // softmax -> out accumulation (+ wh fp16 on non-last layers)
        softmax_causal_acc<<<NTOK, 256>>>(p0, p1, wh, out,
                                          l == 0 ? 1 : 0, last ? 0 : 1);

        if (last) break;   // wv / out-proj / x are dead beyond this point

        // wv partials = w @ v  (split-K x4: balances the KLIM single wave)
        gemm_mma<4, false, true><<<dim3(8, 16, 4), 256, SMEM_BYTES>>>(
            wh, NTOK, vT, NTOK, sp0, sp1, sp2, sp3, EDIM, NTOK, 1.0f);
        combine_split4<<<(NTOK * EDIM / 4 + 511) / 512, 512>>>(
            sp0, sp1, sp2, sp3, nullptr, wv, EDIM, NTOK * EDIM / 4);

        // x partials = wv @ Wo^T  (split-K x2, balanced single wave)
        gemm_mma<2, false, false><<<dim3(8, 16, 2), 256, SMEM_BYTES>>>(
            wv, EDIM, Woh, EDIM, sp0, sp1, sp0, sp1, EDIM, EDIM, 1.0f);
        combine_split<<<(NTOK * EDIM / 4 + 255) / 256, 256>>>(
            sp0, sp1, bl, x, EDIM, NTOK * EDIM / 4);
    }
}